// round 1
// baseline (speedup 1.0000x reference)
#include <cuda_runtime.h>
#include <cstdint>

#define NV 100000
#define NC 100000
#define NTOT 200000
#define D 64
#define CLUSTERS 2048
#define GAMMA 1.0f
#define NEG_SLOPE 0.2f

typedef unsigned long long ull;

// ---------------- scratch (device globals; no allocation allowed) ----------
__device__ __align__(16) float g_Q[NTOT * D];
__device__ __align__(16) float g_K[NTOT * D];
__device__ __align__(16) float g_V[NTOT * D];
__device__ __align__(16) float g_acc[NTOT * D];
__device__ __align__(16) float g_cnt[NTOT];

// ---------------- packed f32x2 helpers (Blackwell FFMA2 path) --------------
__device__ __forceinline__ ull pk(float lo, float hi) {
    ull r;
    asm("mov.b64 %0, {%1, %2};" : "=l"(r) : "f"(lo), "f"(hi));
    return r;
}
__device__ __forceinline__ void upk(ull v, float& lo, float& hi) {
    asm("mov.b64 {%0, %1}, %2;" : "=f"(lo), "=f"(hi) : "l"(v));
}
__device__ __forceinline__ ull fma2(ull a, ull b, ull c) {
    ull d;
    asm("fma.rn.f32x2 %0, %1, %2, %3;" : "=l"(d) : "l"(a), "l"(b), "l"(c));
    return d;
}

// ---------------- zero scratch --------------------------------------------
__global__ void zero_kernel() {
    int idx = blockIdx.x * blockDim.x + threadIdx.x;
    const int n4 = NTOT * D / 4;
    if (idx < n4) ((float4*)g_acc)[idx] = make_float4(0.f, 0.f, 0.f, 0.f);
    if (idx < NTOT) g_cnt[idx] = 0.f;
}

// ---------------- QKV: rows x (3 x 64x64) GEMM ----------------------------
// Block: 256 threads. Each block handles 4 tiles of 32 rows.
// smem: 3 transposed weights [k*65+j] (pad 65 -> conflict-free), x tile
// stored transposed-pair-friendly [k*34 + r] (pad 34 keeps 8B alignment,
// 2-way write conflict only).
#define QKV_SMEM_FLOATS (3 * 64 * 65 + 64 * 34)   // 14656 floats = 58624 B

__global__ void __launch_bounds__(256) qkv_kernel(
    const float* __restrict__ xv, const float* __restrict__ xc,
    const float* __restrict__ WQ, const float* __restrict__ WK,
    const float* __restrict__ WV)
{
    extern __shared__ float sm[];
    float* sW = sm;              // [3][64*65]
    float* sx = sm + 3 * 4160;   // [64*34]
    const int tid = threadIdx.x;

    for (int i = tid; i < 4096; i += 256) {
        int j = i >> 6, k = i & 63;               // W[j][k]
        sW[0 * 4160 + k * 65 + j] = WQ[i];
        sW[1 * 4160 + k * 65 + j] = WK[i];
        sW[2 * 4160 + k * 65 + j] = WV[i];
    }

    const int j = tid & 63;
    const int g = tid >> 6;                        // 0..3 -> rows [8g, 8g+8)

    for (int pass = 0; pass < 4; ++pass) {
        int tile = blockIdx.x * 4 + pass;
        if (tile >= 6250) break;                   // uniform per block
        int r0 = tile * 32;
        const float* src = (r0 < NV) ? (xv + (size_t)r0 * 64)
                                     : (xc + (size_t)(r0 - NV) * 64);
        __syncthreads();
        for (int i = tid; i < 2048; i += 256) {
            int row = i >> 6, k = i & 63;
            sx[k * 34 + row] = src[i];
        }
        __syncthreads();

        ull aq[4], ak[4], av[4];
        #pragma unroll
        for (int p = 0; p < 4; ++p) { aq[p] = 0ull; ak[p] = 0ull; av[p] = 0ull; }

        #pragma unroll 8
        for (int k = 0; k < 64; ++k) {
            float wq = sW[k * 65 + j];
            float wk = sW[4160 + k * 65 + j];
            float wv = sW[8320 + k * 65 + j];
            ull wq2 = pk(wq, wq), wk2 = pk(wk, wk), wv2 = pk(wv, wv);
            #pragma unroll
            for (int p = 0; p < 4; ++p) {
                ull x2 = *(const ull*)&sx[k * 34 + g * 8 + 2 * p];
                aq[p] = fma2(x2, wq2, aq[p]);
                ak[p] = fma2(x2, wk2, ak[p]);
                av[p] = fma2(x2, wv2, av[p]);
            }
        }

        #pragma unroll
        for (int p = 0; p < 4; ++p) {
            int r = r0 + g * 8 + 2 * p;
            float lo, hi;
            upk(aq[p], lo, hi); g_Q[(size_t)r * 64 + j] = lo; g_Q[(size_t)(r + 1) * 64 + j] = hi;
            upk(ak[p], lo, hi); g_K[(size_t)r * 64 + j] = lo; g_K[(size_t)(r + 1) * 64 + j] = hi;
            upk(av[p], lo, hi); g_V[(size_t)r * 64 + j] = lo; g_V[(size_t)(r + 1) * 64 + j] = hi;
        }
    }
}

// ---------------- per-cluster attention -----------------------------------
// One CTA (256 threads) per cluster. smem: Q[128x64], K^T[64x130],
// V[128x64], P[128x128].
#define ATTN_SMEM_FLOATS (8192 + 64 * 130 + 8192 + 128 * 128)  // 41088 = 164352 B

__global__ void __launch_bounds__(256) attn_kernel(
    const int* __restrict__ cvi, const int* __restrict__ cci,
    const float* __restrict__ sat, const int* __restrict__ active_heads,
    const float* __restrict__ head_weights)
{
    extern __shared__ float sm[];
    float* sQ  = sm;               // 8192
    float* sKT = sm + 8192;        // 8320 (64 x 130)
    float* sV  = sm + 16512;       // 8192
    float* sP  = sm + 24704;       // 16384
    __shared__ int   sNode[128];
    __shared__ float sBias[128];
    __shared__ float sHw;

    const int tid = threadIdx.x;
    const int c   = blockIdx.x;

    if (tid < 64) {
        sNode[tid] = cvi[c * 64 + tid];
        sBias[tid] = 0.f;
    } else if (tid < 128) {
        int id = cci[c * 64 + tid - 64];
        sNode[tid] = NV + id;
        sBias[tid] = GAMMA * sat[id];
    }
    if (tid == 0) {
        int ah = active_heads[0];
        if (ah < 1) ah = 1;
        if (ah > 4) ah = 4;
        float s = 0.f;
        for (int h = 0; h < ah; ++h) s += head_weights[h];
        sHw = s / (float)ah;
    }
    __syncthreads();

    // gather Q/K/V rows for this cluster
    for (int i = tid; i < 2048; i += 256) {
        int row = i >> 4, q4 = i & 15;
        size_t base = (size_t)sNode[row] * 64 + q4 * 4;
        float4 fq = *(const float4*)&g_Q[base];
        *(float4*)&sQ[row * 64 + q4 * 4] = fq;
        float4 fk = *(const float4*)&g_K[base];
        int kb = q4 * 4;
        sKT[(kb + 0) * 130 + row] = fk.x;
        sKT[(kb + 1) * 130 + row] = fk.y;
        sKT[(kb + 2) * 130 + row] = fk.z;
        sKT[(kb + 3) * 130 + row] = fk.w;
        float4 fv = *(const float4*)&g_V[base];
        *(float4*)&sV[row * 64 + q4 * 4] = fv;
    }
    __syncthreads();

    // scores = leaky_relu(QK^T / 8 + bias[t]); each thread does 8x8 tile
    {
        const int ts = tid >> 4, tt = tid & 15;
        const int s0 = ts * 8, t0 = tt * 8;
        ull acc[8][4];
        #pragma unroll
        for (int i = 0; i < 8; ++i)
            #pragma unroll
            for (int jj = 0; jj < 4; ++jj) acc[i][jj] = 0ull;

        #pragma unroll 4
        for (int k = 0; k < 64; ++k) {
            ull q2[8];
            #pragma unroll
            for (int i = 0; i < 8; ++i) {
                float q = sQ[(s0 + i) * 64 + k];
                q2[i] = pk(q, q);
            }
            ull kt[4];
            #pragma unroll
            for (int jj = 0; jj < 4; ++jj)
                kt[jj] = *(const ull*)&sKT[k * 130 + t0 + 2 * jj];
            #pragma unroll
            for (int i = 0; i < 8; ++i)
                #pragma unroll
                for (int jj = 0; jj < 4; ++jj)
                    acc[i][jj] = fma2(q2[i], kt[jj], acc[i][jj]);
        }

        const float inv_scale = 0.125f;   // 1/sqrt(64)
        #pragma unroll
        for (int i = 0; i < 8; ++i) {
            int s = s0 + i;
            #pragma unroll
            for (int jj = 0; jj < 4; ++jj) {
                float lo, hi;
                upk(acc[i][jj], lo, hi);
                int t = t0 + 2 * jj;
                float a = lo * inv_scale + sBias[t];
                float b = hi * inv_scale + sBias[t + 1];
                a = (a > 0.f) ? a : NEG_SLOPE * a;
                b = (b > 0.f) ? b : NEG_SLOPE * b;
                *(float2*)&sP[s * 128 + t] = make_float2(a, b);
            }
        }
    }
    __syncthreads();

    // softmax over rows of sP: each warp handles 16 rows
    {
        const int w = tid >> 5, lane = tid & 31;
        for (int r = w * 16; r < w * 16 + 16; ++r) {
            float v[4];
            #pragma unroll
            for (int q = 0; q < 4; ++q) v[q] = sP[r * 128 + lane + q * 32];
            float m = fmaxf(fmaxf(v[0], v[1]), fmaxf(v[2], v[3]));
            #pragma unroll
            for (int o = 16; o > 0; o >>= 1)
                m = fmaxf(m, __shfl_xor_sync(0xffffffffu, m, o));
            float sum = 0.f;
            #pragma unroll
            for (int q = 0; q < 4; ++q) { v[q] = __expf(v[q] - m); sum += v[q]; }
            #pragma unroll
            for (int o = 16; o > 0; o >>= 1)
                sum += __shfl_xor_sync(0xffffffffu, sum, o);
            float inv = 1.0f / sum;
            #pragma unroll
            for (int q = 0; q < 4; ++q) sP[r * 128 + lane + q * 32] = v[q] * inv;
        }
    }
    __syncthreads();

    // h = P @ V * head_w, scatter-add into g_acc / g_cnt
    {
        const int sgrp = tid >> 4, dgrp = tid & 15;
        const int s0 = sgrp * 8, d0 = dgrp * 4;
        ull acc[8][2];
        #pragma unroll
        for (int i = 0; i < 8; ++i) { acc[i][0] = 0ull; acc[i][1] = 0ull; }

        #pragma unroll 4
        for (int t = 0; t < 128; ++t) {
            ull v0 = *(const ull*)&sV[t * 64 + d0];
            ull v1 = *(const ull*)&sV[t * 64 + d0 + 2];
            #pragma unroll
            for (int i = 0; i < 8; ++i) {
                float p = sP[(s0 + i) * 128 + t];
                ull p2 = pk(p, p);
                acc[i][0] = fma2(p2, v0, acc[i][0]);
                acc[i][1] = fma2(p2, v1, acc[i][1]);
            }
        }

        float hw = sHw;
        #pragma unroll
        for (int i = 0; i < 8; ++i) {
            int s = s0 + i;
            int node = sNode[s];
            float* dst = &g_acc[(size_t)node * 64 + d0];
            float a, b;
            upk(acc[i][0], a, b);
            atomicAdd(dst + 0, a * hw);
            atomicAdd(dst + 1, b * hw);
            upk(acc[i][1], a, b);
            atomicAdd(dst + 2, a * hw);
            atomicAdd(dst + 3, b * hw);
            if (dgrp == 0) atomicAdd(&g_cnt[node], 1.0f);
        }
    }
}

// ---------------- projection + residual -----------------------------------
__global__ void __launch_bounds__(256) proj_kernel(
    const float* __restrict__ xv, const float* __restrict__ xc,
    const float* __restrict__ Wout, const float* __restrict__ bout,
    float* __restrict__ out)
{
    __shared__ float sW[64 * 65];
    __shared__ float sx[64 * 34];
    __shared__ float sb[64];
    const int tid = threadIdx.x;

    for (int i = tid; i < 4096; i += 256) {
        int j = i >> 6, k = i & 63;
        sW[k * 65 + j] = Wout[i];
    }
    if (tid < 64) sb[tid] = bout[tid];

    const int j = tid & 63;
    const int g = tid >> 6;

    for (int pass = 0; pass < 4; ++pass) {
        int tile = blockIdx.x * 4 + pass;
        if (tile >= 6250) break;
        int r0 = tile * 32;
        __syncthreads();
        for (int i = tid; i < 2048; i += 256) {
            int row = i >> 6, k = i & 63;
            float cnt = g_cnt[r0 + row];
            sx[k * 34 + row] = g_acc[(size_t)r0 * 64 + i] / fmaxf(cnt, 1.0f);
        }
        __syncthreads();

        ull a[4];
        #pragma unroll
        for (int p = 0; p < 4; ++p) a[p] = 0ull;

        #pragma unroll 8
        for (int k = 0; k < 64; ++k) {
            float w = sW[k * 65 + j];
            ull w2 = pk(w, w);
            #pragma unroll
            for (int p = 0; p < 4; ++p) {
                ull x2 = *(const ull*)&sx[k * 34 + g * 8 + 2 * p];
                a[p] = fma2(x2, w2, a[p]);
            }
        }

        const float* xsrc = (r0 < NV) ? (xv + (size_t)r0 * 64)
                                      : (xc + (size_t)(r0 - NV) * 64);
        float bj = sb[j];
        #pragma unroll
        for (int p = 0; p < 4; ++p) {
            int r = g * 8 + 2 * p;
            float lo, hi;
            upk(a[p], lo, hi);
            out[(size_t)(r0 + r) * 64 + j]     = xsrc[(size_t)r * 64 + j] + bj + lo;
            out[(size_t)(r0 + r + 1) * 64 + j] = xsrc[(size_t)(r + 1) * 64 + j] + bj + hi;
        }
    }
}

// ---------------- launcher -------------------------------------------------
extern "C" void kernel_launch(void* const* d_in, const int* in_sizes, int n_in,
                              void* d_out, int out_size)
{
    const float* xv   = (const float*)d_in[0];
    const float* xc   = (const float*)d_in[1];
    // d_in[2] edge_index, d_in[3] edge_polarity: unused by reference
    const int*   cvi  = (const int*)d_in[4];
    const int*   cci  = (const int*)d_in[5];
    const float* sat  = (const float*)d_in[6];
    const int*   ah   = (const int*)d_in[7];
    const float* WQ   = (const float*)d_in[8];
    const float* WK   = (const float*)d_in[9];
    const float* WV   = (const float*)d_in[10];
    const float* hw   = (const float*)d_in[11];
    const float* Wout = (const float*)d_in[12];
    const float* bout = (const float*)d_in[13];
    float* out = (float*)d_out;

    const int qkv_smem  = QKV_SMEM_FLOATS * 4;
    const int attn_smem = ATTN_SMEM_FLOATS * 4;
    cudaFuncSetAttribute(qkv_kernel,  cudaFuncAttributeMaxDynamicSharedMemorySize, qkv_smem);
    cudaFuncSetAttribute(attn_kernel, cudaFuncAttributeMaxDynamicSharedMemorySize, attn_smem);

    zero_kernel<<<(NTOT * D / 4 + 255) / 256, 256>>>();
    qkv_kernel<<<1563, 256, qkv_smem>>>(xv, xc, WQ, WK, WV);
    attn_kernel<<<CLUSTERS, 256, attn_smem>>>(cvi, cci, sat, ah, hw);
    proj_kernel<<<1563, 256>>>(xv, xc, Wout, bout, out);
}

// round 2
// speedup vs baseline: 1.1424x; 1.1424x over previous
#include <cuda_runtime.h>
#include <cstdint>

#define NV 100000
#define NC 100000
#define NTOT 200000
#define D 64
#define CLUSTERS 2048
#define GAMMA 1.0f
#define NEG_SLOPE 0.2f

typedef unsigned long long ull;

// ---------------- scratch (device globals; no allocation allowed) ----------
__device__ __align__(16) float g_Q[NTOT * D];
__device__ __align__(16) float g_K[NTOT * D];
__device__ __align__(16) float g_V[NTOT * D];
__device__ __align__(16) float g_acc[NTOT * D];
__device__ __align__(16) float g_cnt[NTOT];

// ---------------- packed f32x2 helpers (Blackwell FFMA2 path) --------------
__device__ __forceinline__ ull pk(float lo, float hi) {
    ull r;
    asm("mov.b64 %0, {%1, %2};" : "=l"(r) : "f"(lo), "f"(hi));
    return r;
}
__device__ __forceinline__ void upk(ull v, float& lo, float& hi) {
    asm("mov.b64 {%0, %1}, %2;" : "=f"(lo), "=f"(hi) : "l"(v));
}
__device__ __forceinline__ ull fma2(ull a, ull b, ull c) {
    ull d;
    asm("fma.rn.f32x2 %0, %1, %2, %3;" : "=l"(d) : "l"(a), "l"(b), "l"(c));
    return d;
}

// ---------------- zero scratch --------------------------------------------
__global__ void zero_kernel() {
    int idx = blockIdx.x * blockDim.x + threadIdx.x;
    const int n4 = NTOT * D / 4;
    if (idx < n4) ((float4*)g_acc)[idx] = make_float4(0.f, 0.f, 0.f, 0.f);
    if (idx < NTOT) g_cnt[idx] = 0.f;
}

// ---------------- QKV: rows x (3 x 64x64) GEMM ----------------------------
// 256 threads, 64-row tiles, 16 rows per thread. 782 blocks x 4 passes.
// smem: 3 transposed weights [k*65+j], x transposed [k*66+row].
#define QKV_SMEM_FLOATS (3 * 64 * 65 + 64 * 66)   // 16704 floats = 66816 B

__global__ void __launch_bounds__(256) qkv_kernel(
    const float* __restrict__ xv, const float* __restrict__ xc,
    const float* __restrict__ WQ, const float* __restrict__ WK,
    const float* __restrict__ WV)
{
    extern __shared__ float sm[];
    float* sW = sm;              // [3][64*65]
    float* sx = sm + 3 * 4160;   // [64*66]
    const int tid = threadIdx.x;

    for (int i = tid; i < 4096; i += 256) {
        int j = i >> 6, k = i & 63;               // W[j][k]
        sW[0 * 4160 + k * 65 + j] = WQ[i];
        sW[1 * 4160 + k * 65 + j] = WK[i];
        sW[2 * 4160 + k * 65 + j] = WV[i];
    }

    const int j = tid & 63;
    const int g = tid >> 6;                        // rows [16g, 16g+16)

    for (int pass = 0; pass < 4; ++pass) {
        int tile = blockIdx.x * 4 + pass;
        if (tile >= 3125) break;                   // uniform per block
        int r0 = tile * 64;
        __syncthreads();
        for (int i = tid; i < 4096; i += 256) {
            int row = i >> 6, k = i & 63;
            int gr = r0 + row;
            float v = (gr < NV) ? xv[(size_t)gr * 64 + k]
                                : xc[(size_t)(gr - NV) * 64 + k];
            sx[k * 66 + row] = v;
        }
        __syncthreads();

        ull aq[8], ak[8], av[8];
        #pragma unroll
        for (int p = 0; p < 8; ++p) { aq[p] = 0ull; ak[p] = 0ull; av[p] = 0ull; }

        #pragma unroll 4
        for (int k = 0; k < 64; ++k) {
            float wq = sW[k * 65 + j];
            float wk = sW[4160 + k * 65 + j];
            float wv = sW[8320 + k * 65 + j];
            ull wq2 = pk(wq, wq), wk2 = pk(wk, wk), wv2 = pk(wv, wv);
            #pragma unroll
            for (int p = 0; p < 8; ++p) {
                ull x2 = *(const ull*)&sx[k * 66 + g * 16 + 2 * p];
                aq[p] = fma2(x2, wq2, aq[p]);
                ak[p] = fma2(x2, wk2, ak[p]);
                av[p] = fma2(x2, wv2, av[p]);
            }
        }

        #pragma unroll
        for (int p = 0; p < 8; ++p) {
            int r = r0 + g * 16 + 2 * p;
            float lo, hi;
            upk(aq[p], lo, hi); g_Q[(size_t)r * 64 + j] = lo; g_Q[(size_t)(r + 1) * 64 + j] = hi;
            upk(ak[p], lo, hi); g_K[(size_t)r * 64 + j] = lo; g_K[(size_t)(r + 1) * 64 + j] = hi;
            upk(av[p], lo, hi); g_V[(size_t)r * 64 + j] = lo; g_V[(size_t)(r + 1) * 64 + j] = hi;
        }
    }
}

// ---------------- per-cluster attention -----------------------------------
// One CTA (256 threads) per cluster, 2 CTAs/SM.
// smem: QT[64x130] + KT[64x130] + V[128x64] = 24832 floats = 99328 B.
// P[128x128] (16384 floats) OVERLAYS QT+KT (16640 floats) after the score
// phase — Q/K are dead once scores are in registers.
#define ATTN_SMEM_FLOATS (8320 + 8320 + 8192)   // 99328 B

__global__ void __launch_bounds__(256, 2) attn_kernel(
    const int* __restrict__ cvi, const int* __restrict__ cci,
    const float* __restrict__ sat, const int* __restrict__ active_heads,
    const float* __restrict__ head_weights)
{
    extern __shared__ float sm[];
    float* sQT = sm;               // 8320 (64 x 130)
    float* sKT = sm + 8320;        // 8320 (64 x 130)
    float* sV  = sm + 16640;       // 8192 (128 x 64)
    float* sP  = sm;               // 16384, overlays QT+KT
    __shared__ int   sNode[128];
    __shared__ float sBias[128];
    __shared__ float sHw;

    const int tid = threadIdx.x;
    const int c   = blockIdx.x;

    if (tid < 64) {
        sNode[tid] = cvi[c * 64 + tid];
        sBias[tid] = 0.f;
    } else if (tid < 128) {
        int id = cci[c * 64 + tid - 64];
        sNode[tid] = NV + id;
        sBias[tid] = GAMMA * sat[id];
    }
    if (tid == 0) {
        int ah = active_heads[0];
        if (ah < 1) ah = 1;
        if (ah > 4) ah = 4;
        float s = 0.f;
        for (int h = 0; h < ah; ++h) s += head_weights[h];
        sHw = s / (float)ah;
    }
    __syncthreads();

    // gather Q/K/V rows for this cluster (Q and K stored transposed)
    for (int i = tid; i < 2048; i += 256) {
        int row = i >> 4, q4 = i & 15;
        size_t base = (size_t)sNode[row] * 64 + q4 * 4;
        int kb = q4 * 4;
        float4 fq = *(const float4*)&g_Q[base];
        sQT[(kb + 0) * 130 + row] = fq.x;
        sQT[(kb + 1) * 130 + row] = fq.y;
        sQT[(kb + 2) * 130 + row] = fq.z;
        sQT[(kb + 3) * 130 + row] = fq.w;
        float4 fk = *(const float4*)&g_K[base];
        sKT[(kb + 0) * 130 + row] = fk.x;
        sKT[(kb + 1) * 130 + row] = fk.y;
        sKT[(kb + 2) * 130 + row] = fk.z;
        sKT[(kb + 3) * 130 + row] = fk.w;
        float4 fv = *(const float4*)&g_V[base];
        *(float4*)&sV[row * 64 + q4 * 4] = fv;
    }
    __syncthreads();

    // scores (registers): each thread an 8x8 tile
    const int ts = tid >> 4, tt = tid & 15;
    const int s0 = ts * 8, t0 = tt * 8;
    ull acc[8][4];
    #pragma unroll
    for (int i = 0; i < 8; ++i)
        #pragma unroll
        for (int jj = 0; jj < 4; ++jj) acc[i][jj] = 0ull;

    #pragma unroll 4
    for (int k = 0; k < 64; ++k) {
        float q[8];
        #pragma unroll
        for (int i = 0; i < 4; ++i) {
            ull qp = *(const ull*)&sQT[k * 130 + s0 + 2 * i];
            upk(qp, q[2 * i], q[2 * i + 1]);
        }
        ull kt[4];
        #pragma unroll
        for (int jj = 0; jj < 4; ++jj)
            kt[jj] = *(const ull*)&sKT[k * 130 + t0 + 2 * jj];
        #pragma unroll
        for (int i = 0; i < 8; ++i) {
            ull q2 = pk(q[i], q[i]);
            #pragma unroll
            for (int jj = 0; jj < 4; ++jj)
                acc[i][jj] = fma2(q2, kt[jj], acc[i][jj]);
        }
    }

    __syncthreads();   // Q/K reads complete -> safe to overlay P

    // bias + leaky_relu, write P
    {
        const float inv_scale = 0.125f;   // 1/sqrt(64)
        #pragma unroll
        for (int i = 0; i < 8; ++i) {
            int s = s0 + i;
            #pragma unroll
            for (int jj = 0; jj < 4; ++jj) {
                float lo, hi;
                upk(acc[i][jj], lo, hi);
                int t = t0 + 2 * jj;
                float a = lo * inv_scale + sBias[t];
                float b = hi * inv_scale + sBias[t + 1];
                a = (a > 0.f) ? a : NEG_SLOPE * a;
                b = (b > 0.f) ? b : NEG_SLOPE * b;
                *(float2*)&sP[s * 128 + t] = make_float2(a, b);
            }
        }
    }
    __syncthreads();

    // softmax over rows of sP: each warp handles 16 rows
    {
        const int w = tid >> 5, lane = tid & 31;
        for (int r = w * 16; r < w * 16 + 16; ++r) {
            float v[4];
            #pragma unroll
            for (int q = 0; q < 4; ++q) v[q] = sP[r * 128 + lane + q * 32];
            float m = fmaxf(fmaxf(v[0], v[1]), fmaxf(v[2], v[3]));
            #pragma unroll
            for (int o = 16; o > 0; o >>= 1)
                m = fmaxf(m, __shfl_xor_sync(0xffffffffu, m, o));
            float sum = 0.f;
            #pragma unroll
            for (int q = 0; q < 4; ++q) { v[q] = __expf(v[q] - m); sum += v[q]; }
            #pragma unroll
            for (int o = 16; o > 0; o >>= 1)
                sum += __shfl_xor_sync(0xffffffffu, sum, o);
            float inv = 1.0f / sum;
            #pragma unroll
            for (int q = 0; q < 4; ++q) sP[r * 128 + lane + q * 32] = v[q] * inv;
        }
    }
    __syncthreads();

    // h = P @ V * head_w, scatter-add into g_acc / g_cnt
    {
        const int sgrp = tid >> 4, dgrp = tid & 15;
        const int ss0 = sgrp * 8, d0 = dgrp * 4;
        ull hacc[8][2];
        #pragma unroll
        for (int i = 0; i < 8; ++i) { hacc[i][0] = 0ull; hacc[i][1] = 0ull; }

        #pragma unroll 4
        for (int t = 0; t < 128; ++t) {
            ull v0 = *(const ull*)&sV[t * 64 + d0];
            ull v1 = *(const ull*)&sV[t * 64 + d0 + 2];
            #pragma unroll
            for (int i = 0; i < 8; ++i) {
                float p = sP[(ss0 + i) * 128 + t];
                ull p2 = pk(p, p);
                hacc[i][0] = fma2(p2, v0, hacc[i][0]);
                hacc[i][1] = fma2(p2, v1, hacc[i][1]);
            }
        }

        float hw = sHw;
        #pragma unroll
        for (int i = 0; i < 8; ++i) {
            int s = ss0 + i;
            int node = sNode[s];
            float* dst = &g_acc[(size_t)node * 64 + d0];
            float a, b;
            upk(hacc[i][0], a, b);
            atomicAdd(dst + 0, a * hw);
            atomicAdd(dst + 1, b * hw);
            upk(hacc[i][1], a, b);
            atomicAdd(dst + 2, a * hw);
            atomicAdd(dst + 3, b * hw);
            if (dgrp == 0) atomicAdd(&g_cnt[node], 1.0f);
        }
    }
}

// ---------------- projection + residual -----------------------------------
// 256 threads, 64-row tiles, 16 rows per thread. 782 blocks x 4 passes.
__global__ void __launch_bounds__(256) proj_kernel(
    const float* __restrict__ xv, const float* __restrict__ xc,
    const float* __restrict__ Wout, const float* __restrict__ bout,
    float* __restrict__ out)
{
    __shared__ float sW[64 * 65];
    __shared__ float sx[64 * 66];
    __shared__ float sb[64];
    __shared__ float sRc[64];
    const int tid = threadIdx.x;

    for (int i = tid; i < 4096; i += 256) {
        int j = i >> 6, k = i & 63;
        sW[k * 65 + j] = Wout[i];
    }
    if (tid < 64) sb[tid] = bout[tid];

    const int j = tid & 63;
    const int g = tid >> 6;

    for (int pass = 0; pass < 4; ++pass) {
        int tile = blockIdx.x * 4 + pass;
        if (tile >= 3125) break;
        int r0 = tile * 64;
        __syncthreads();
        if (tid < 64) sRc[tid] = 1.0f / fmaxf(g_cnt[r0 + tid], 1.0f);
        __syncthreads();
        for (int i = tid; i < 1024; i += 256) {
            int row = i >> 4, q4 = i & 15;
            float4 f = *(const float4*)&g_acc[(size_t)(r0 + row) * 64 + q4 * 4];
            float rc = sRc[row];
            int kb = q4 * 4;
            sx[(kb + 0) * 66 + row] = f.x * rc;
            sx[(kb + 1) * 66 + row] = f.y * rc;
            sx[(kb + 2) * 66 + row] = f.z * rc;
            sx[(kb + 3) * 66 + row] = f.w * rc;
        }
        __syncthreads();

        ull a[8];
        #pragma unroll
        for (int p = 0; p < 8; ++p) a[p] = 0ull;

        #pragma unroll 4
        for (int k = 0; k < 64; ++k) {
            float w = sW[k * 65 + j];
            ull w2 = pk(w, w);
            #pragma unroll
            for (int p = 0; p < 8; ++p) {
                ull x2 = *(const ull*)&sx[k * 66 + g * 16 + 2 * p];
                a[p] = fma2(x2, w2, a[p]);
            }
        }

        float bj = sb[j];
        #pragma unroll
        for (int p = 0; p < 8; ++p) {
            int gr = r0 + g * 16 + 2 * p;
            float lo, hi;
            upk(a[p], lo, hi);
            float x0 = (gr < NV) ? xv[(size_t)gr * 64 + j]
                                 : xc[(size_t)(gr - NV) * 64 + j];
            float x1 = (gr + 1 < NV) ? xv[(size_t)(gr + 1) * 64 + j]
                                     : xc[(size_t)(gr + 1 - NV) * 64 + j];
            out[(size_t)gr * 64 + j]       = x0 + bj + lo;
            out[(size_t)(gr + 1) * 64 + j] = x1 + bj + hi;
        }
    }
}

// ---------------- launcher -------------------------------------------------
extern "C" void kernel_launch(void* const* d_in, const int* in_sizes, int n_in,
                              void* d_out, int out_size)
{
    const float* xv   = (const float*)d_in[0];
    const float* xc   = (const float*)d_in[1];
    // d_in[2] edge_index, d_in[3] edge_polarity: unused by reference
    const int*   cvi  = (const int*)d_in[4];
    const int*   cci  = (const int*)d_in[5];
    const float* sat  = (const float*)d_in[6];
    const int*   ah   = (const int*)d_in[7];
    const float* WQ   = (const float*)d_in[8];
    const float* WK   = (const float*)d_in[9];
    const float* WV   = (const float*)d_in[10];
    const float* hw   = (const float*)d_in[11];
    const float* Wout = (const float*)d_in[12];
    const float* bout = (const float*)d_in[13];
    float* out = (float*)d_out;

    const int qkv_smem  = QKV_SMEM_FLOATS * 4;
    const int attn_smem = ATTN_SMEM_FLOATS * 4;
    cudaFuncSetAttribute(qkv_kernel,  cudaFuncAttributeMaxDynamicSharedMemorySize, qkv_smem);
    cudaFuncSetAttribute(attn_kernel, cudaFuncAttributeMaxDynamicSharedMemorySize, attn_smem);

    zero_kernel<<<(NTOT * D / 4 + 255) / 256, 256>>>();
    qkv_kernel<<<782, 256, qkv_smem>>>(xv, xc, WQ, WK, WV);
    attn_kernel<<<CLUSTERS, 256, attn_smem>>>(cvi, cci, sat, ah, hw);
    proj_kernel<<<782, 256>>>(xv, xc, Wout, bout, out);
}

// round 4
// speedup vs baseline: 1.1700x; 1.0241x over previous
#include <cuda_runtime.h>
#include <cuda_bf16.h>
#include <cstdint>

#define NV 100000
#define NC 100000
#define NTOT 200000
#define D 64
#define CLUSTERS 2048
#define GAMMA 1.0f
#define NEG_SLOPE 0.2f

typedef unsigned long long ull;

// ---------------- scratch (device globals; no allocation allowed) ----------
__device__ __align__(16) float g_Q[NTOT * D];
__device__ __align__(16) float g_K[NTOT * D];
__device__ __align__(16) float g_V[NTOT * D];
__device__ __align__(16) float g_acc[NTOT * D];
__device__ __align__(16) float g_cnt[NTOT];

// ---------------- packed f32x2 helpers -------------------------------------
__device__ __forceinline__ ull pk(float lo, float hi) {
    ull r;
    asm("mov.b64 %0, {%1, %2};" : "=l"(r) : "f"(lo), "f"(hi));
    return r;
}
__device__ __forceinline__ void upk(ull v, float& lo, float& hi) {
    asm("mov.b64 {%0, %1}, %2;" : "=f"(lo), "=f"(hi) : "l"(v));
}
__device__ __forceinline__ ull fma2(ull a, ull b, ull c) {
    ull d;
    asm("fma.rn.f32x2 %0, %1, %2, %3;" : "=l"(d) : "l"(a), "l"(b), "l"(c));
    return d;
}

// split float pair into (hi, lo) bf16x2 words; lower half = first element
__device__ __forceinline__ void bf2split(float a, float b, uint32_t& hi, uint32_t& lo) {
    __nv_bfloat162 h = __floats2bfloat162_rn(a, b);
    float ha = __bfloat162float(__low2bfloat16(h));
    float hb = __bfloat162float(__high2bfloat16(h));
    __nv_bfloat162 l = __floats2bfloat162_rn(a - ha, b - hb);
    hi = *reinterpret_cast<uint32_t*>(&h);
    lo = *reinterpret_cast<uint32_t*>(&l);
}

// mma.sync m16n8k16 bf16 -> f32 accumulate
__device__ __forceinline__ void mma16816(float* c, uint32_t a0, uint32_t a1,
                                         uint32_t a2, uint32_t a3,
                                         uint32_t b0, uint32_t b1) {
    asm volatile(
        "mma.sync.aligned.m16n8k16.row.col.f32.bf16.bf16.f32 "
        "{%0,%1,%2,%3}, {%4,%5,%6,%7}, {%8,%9}, {%0,%1,%2,%3};"
        : "+f"(c[0]), "+f"(c[1]), "+f"(c[2]), "+f"(c[3])
        : "r"(a0), "r"(a1), "r"(a2), "r"(a3), "r"(b0), "r"(b1));
}

// ---------------- zero scratch --------------------------------------------
__global__ void zero_kernel() {
    int idx = blockIdx.x * blockDim.x + threadIdx.x;
    const int n4 = NTOT * D / 4;
    if (idx < n4) ((float4*)g_acc)[idx] = make_float4(0.f, 0.f, 0.f, 0.f);
    if (idx < NTOT) g_cnt[idx] = 0.f;
}

// ---------------- QKV: rows x (3 x 64x64) GEMM ----------------------------
#define QKV_SMEM_FLOATS (3 * 64 * 65 + 64 * 66)

__global__ void __launch_bounds__(256) qkv_kernel(
    const float* __restrict__ xv, const float* __restrict__ xc,
    const float* __restrict__ WQ, const float* __restrict__ WK,
    const float* __restrict__ WV)
{
    extern __shared__ float smq[];
    float* sW = smq;
    float* sx = smq + 3 * 4160;
    const int tid = threadIdx.x;

    for (int i = tid; i < 4096; i += 256) {
        int j = i >> 6, k = i & 63;
        sW[0 * 4160 + k * 65 + j] = WQ[i];
        sW[1 * 4160 + k * 65 + j] = WK[i];
        sW[2 * 4160 + k * 65 + j] = WV[i];
    }

    const int j = tid & 63;
    const int g = tid >> 6;
    const int r0 = blockIdx.x * 64;

    for (int i = tid; i < 4096; i += 256) {
        int row = i >> 6, k = i & 63;
        int gr = r0 + row;
        float v = (gr < NV) ? xv[(size_t)gr * 64 + k]
                            : xc[(size_t)(gr - NV) * 64 + k];
        sx[k * 66 + row] = v;
    }
    __syncthreads();

    ull aq[8], ak[8], av[8];
    #pragma unroll
    for (int p = 0; p < 8; ++p) { aq[p] = 0ull; ak[p] = 0ull; av[p] = 0ull; }

    #pragma unroll 4
    for (int k = 0; k < 64; ++k) {
        float wq = sW[k * 65 + j];
        float wk = sW[4160 + k * 65 + j];
        float wv = sW[8320 + k * 65 + j];
        ull wq2 = pk(wq, wq), wk2 = pk(wk, wk), wv2 = pk(wv, wv);
        #pragma unroll
        for (int p = 0; p < 8; ++p) {
            ull x2 = *(const ull*)&sx[k * 66 + g * 16 + 2 * p];
            aq[p] = fma2(x2, wq2, aq[p]);
            ak[p] = fma2(x2, wk2, ak[p]);
            av[p] = fma2(x2, wv2, av[p]);
        }
    }

    #pragma unroll
    for (int p = 0; p < 8; ++p) {
        int r = r0 + g * 16 + 2 * p;
        float lo, hi;
        upk(aq[p], lo, hi); g_Q[(size_t)r * 64 + j] = lo; g_Q[(size_t)(r + 1) * 64 + j] = hi;
        upk(ak[p], lo, hi); g_K[(size_t)r * 64 + j] = lo; g_K[(size_t)(r + 1) * 64 + j] = hi;
        upk(av[p], lo, hi); g_V[(size_t)r * 64 + j] = lo; g_V[(size_t)(r + 1) * 64 + j] = hi;
    }
}

// ---------------- HMMA attention ------------------------------------------
// One CTA (8 warps) per cluster. Each warp: 16-row stripe.
// smem (bytes):
//   Qhi/Qlo: [128 rows][72 bf16] stride 144B  -> 18432 each
//   Khi/Klo: same                              -> 18432 each
//   VThi/VTlo: [64 d][136 bf16] stride 272B    -> 17408 each
#define A_QHI 0
#define A_QLO 18432
#define A_KHI 36864
#define A_KLO 55296
#define A_VHI 73728
#define A_VLO 91136
#define ATTN_SMEM_BYTES 108544

__global__ void __launch_bounds__(256) attn_kernel(
    const int* __restrict__ cvi, const int* __restrict__ cci,
    const float* __restrict__ sat, const int* __restrict__ active_heads,
    const float* __restrict__ head_weights)
{
    extern __shared__ char smc[];
    __shared__ int   sNode[128];
    __shared__ float sBias[128];
    __shared__ float sHw;

    const int tid  = threadIdx.x;
    const int wid  = tid >> 5;
    const int lane = tid & 31;
    const int c    = blockIdx.x;
    const int g    = lane >> 2;        // 0..7
    const int t    = lane & 3;         // 0..3
    const int m0   = wid * 16;

    if (tid < 64) {
        sNode[tid] = cvi[c * 64 + tid];
        sBias[tid] = 0.f;
    } else if (tid < 128) {
        int id = cci[c * 64 + tid - 64];
        sNode[tid] = NV + id;
        sBias[tid] = GAMMA * sat[id];
    }
    if (tid == 128) {
        int ah = active_heads[0];
        if (ah < 1) ah = 1;
        if (ah > 4) ah = 4;
        float s = 0.f;
        for (int h = 0; h < 4; ++h) if (h < ah) s += head_weights[h];
        sHw = s / (float)ah;
    }
    __syncthreads();

    // ---- gather + split to bf16 hi/lo ----
    {
        const int row = tid >> 1;
        const int h32 = (tid & 1) * 32;
        const int node = sNode[row];
        const float* qp = g_Q + (size_t)node * 64 + h32;
        const float* kp = g_K + (size_t)node * 64 + h32;
        const float* vp = g_V + (size_t)node * 64 + h32;
        #pragma unroll
        for (int i = 0; i < 8; ++i) {
            int d = h32 + i * 4;
            uint32_t hi, lo;
            uint32_t qoff = (uint32_t)row * 144 + (uint32_t)d * 2;

            float4 fq = *(const float4*)(qp + i * 4);
            bf2split(fq.x, fq.y, hi, lo);
            *(uint32_t*)(smc + A_QHI + qoff) = hi;
            *(uint32_t*)(smc + A_QLO + qoff) = lo;
            bf2split(fq.z, fq.w, hi, lo);
            *(uint32_t*)(smc + A_QHI + qoff + 4) = hi;
            *(uint32_t*)(smc + A_QLO + qoff + 4) = lo;

            float4 fk = *(const float4*)(kp + i * 4);
            bf2split(fk.x, fk.y, hi, lo);
            *(uint32_t*)(smc + A_KHI + qoff) = hi;
            *(uint32_t*)(smc + A_KLO + qoff) = lo;
            bf2split(fk.z, fk.w, hi, lo);
            *(uint32_t*)(smc + A_KHI + qoff + 4) = hi;
            *(uint32_t*)(smc + A_KLO + qoff + 4) = lo;

            float4 fv = *(const float4*)(vp + i * 4);
            float vv[4] = {fv.x, fv.y, fv.z, fv.w};
            #pragma unroll
            for (int q = 0; q < 4; ++q) {
                __nv_bfloat16 vh = __float2bfloat16_rn(vv[q]);
                __nv_bfloat16 vl = __float2bfloat16_rn(vv[q] - __bfloat162float(vh));
                uint32_t vo = (uint32_t)(d + q) * 272 + (uint32_t)row * 2;
                *(__nv_bfloat16*)(smc + A_VHI + vo) = vh;
                *(__nv_bfloat16*)(smc + A_VLO + vo) = vl;
            }
        }
    }
    __syncthreads();

    // ---- S = Q K^T via 3-pass bf16-split HMMA ----
    float cS[16][4];
    #pragma unroll
    for (int n = 0; n < 16; ++n)
        #pragma unroll
        for (int j = 0; j < 4; ++j) cS[n][j] = 0.f;

    const uint32_t qrowA = (uint32_t)(m0 + g) * 144;
    const uint32_t qrowB = qrowA + 8 * 144;

    #pragma unroll 1
    for (int pass = 0; pass < 3; ++pass) {
        const char* qb = smc + ((pass == 2) ? A_QLO : A_QHI);
        const char* kb = smc + ((pass == 1) ? A_KLO : A_KHI);
        #pragma unroll
        for (int kc = 0; kc < 4; ++kc) {
            uint32_t ko = (uint32_t)kc * 32 + (uint32_t)t * 4;
            uint32_t a0 = *(const uint32_t*)(qb + qrowA + ko);
            uint32_t a1 = *(const uint32_t*)(qb + qrowB + ko);
            uint32_t a2 = *(const uint32_t*)(qb + qrowA + ko + 16);
            uint32_t a3 = *(const uint32_t*)(qb + qrowB + ko + 16);
            #pragma unroll
            for (int n = 0; n < 16; ++n) {
                const char* kr = kb + (uint32_t)(8 * n + g) * 144 + ko;
                uint32_t b0 = *(const uint32_t*)kr;
                uint32_t b1 = *(const uint32_t*)(kr + 16);
                mma16816(cS[n], a0, a1, a2, a3, b0, b1);
            }
        }
    }

    // ---- bias + leaky + softmax (rows m0+g and m0+g+8, in registers) ----
    float mA = -1e30f, mB = -1e30f;
    #pragma unroll
    for (int n = 0; n < 16; ++n) {
        float b0v = sBias[8 * n + 2 * t];
        float b1v = sBias[8 * n + 2 * t + 1];
        float s;
        s = cS[n][0] * 0.125f + b0v; s = (s > 0.f) ? s : NEG_SLOPE * s; cS[n][0] = s; mA = fmaxf(mA, s);
        s = cS[n][1] * 0.125f + b1v; s = (s > 0.f) ? s : NEG_SLOPE * s; cS[n][1] = s; mA = fmaxf(mA, s);
        s = cS[n][2] * 0.125f + b0v; s = (s > 0.f) ? s : NEG_SLOPE * s; cS[n][2] = s; mB = fmaxf(mB, s);
        s = cS[n][3] * 0.125f + b1v; s = (s > 0.f) ? s : NEG_SLOPE * s; cS[n][3] = s; mB = fmaxf(mB, s);
    }
    mA = fmaxf(mA, __shfl_xor_sync(0xffffffffu, mA, 1));
    mA = fmaxf(mA, __shfl_xor_sync(0xffffffffu, mA, 2));
    mB = fmaxf(mB, __shfl_xor_sync(0xffffffffu, mB, 1));
    mB = fmaxf(mB, __shfl_xor_sync(0xffffffffu, mB, 2));

    float sA = 0.f, sB = 0.f;
    #pragma unroll
    for (int n = 0; n < 16; ++n) {
        cS[n][0] = __expf(cS[n][0] - mA); sA += cS[n][0];
        cS[n][1] = __expf(cS[n][1] - mA); sA += cS[n][1];
        cS[n][2] = __expf(cS[n][2] - mB); sB += cS[n][2];
        cS[n][3] = __expf(cS[n][3] - mB); sB += cS[n][3];
    }
    sA += __shfl_xor_sync(0xffffffffu, sA, 1);
    sA += __shfl_xor_sync(0xffffffffu, sA, 2);
    sB += __shfl_xor_sync(0xffffffffu, sB, 1);
    sB += __shfl_xor_sync(0xffffffffu, sB, 2);

    const float hw = sHw;
    const float scA = hw / sA;
    const float scB = hw / sB;

    // pack P (hi/lo) directly into A-fragment registers
    uint32_t phi[16][2], plo[16][2];
    #pragma unroll
    for (int n = 0; n < 16; ++n) {
        bf2split(cS[n][0] * scA, cS[n][1] * scA, phi[n][0], plo[n][0]);
        bf2split(cS[n][2] * scB, cS[n][3] * scB, phi[n][1], plo[n][1]);
    }

    // ---- H = P V via 3-pass bf16-split HMMA ----
    float cH[8][4];
    #pragma unroll
    for (int n = 0; n < 8; ++n)
        #pragma unroll
        for (int j = 0; j < 4; ++j) cH[n][j] = 0.f;

    #pragma unroll 1
    for (int pass = 0; pass < 3; ++pass) {
        const uint32_t (*Pa)[2] = (pass == 2) ? plo : phi;
        const char* vb = smc + ((pass == 1) ? A_VLO : A_VHI);
        #pragma unroll
        for (int kc = 0; kc < 8; ++kc) {
            uint32_t a0 = Pa[2 * kc][0];
            uint32_t a1 = Pa[2 * kc][1];
            uint32_t a2 = Pa[2 * kc + 1][0];
            uint32_t a3 = Pa[2 * kc + 1][1];
            uint32_t ko = (uint32_t)kc * 32 + (uint32_t)t * 4;
            #pragma unroll
            for (int n = 0; n < 8; ++n) {
                const char* vr = vb + (uint32_t)(8 * n + g) * 272 + ko;
                uint32_t b0 = *(const uint32_t*)vr;
                uint32_t b1 = *(const uint32_t*)(vr + 16);
                mma16816(cH[n], a0, a1, a2, a3, b0, b1);
            }
        }
    }

    // ---- epilogue: scatter-add ----
    {
        int nodeA = sNode[m0 + g];
        int nodeB = sNode[m0 + g + 8];
        float* dA = g_acc + (size_t)nodeA * 64;
        float* dB = g_acc + (size_t)nodeB * 64;
        #pragma unroll
        for (int n = 0; n < 8; ++n) {
            int col = 8 * n + 2 * t;
            atomicAdd(dA + col,     cH[n][0]);
            atomicAdd(dA + col + 1, cH[n][1]);
            atomicAdd(dB + col,     cH[n][2]);
            atomicAdd(dB + col + 1, cH[n][3]);
        }
        if (t == 0) {
            atomicAdd(&g_cnt[nodeA], 1.0f);
            atomicAdd(&g_cnt[nodeB], 1.0f);
        }
    }
}

// ---------------- projection + residual -----------------------------------
__global__ void __launch_bounds__(256) proj_kernel(
    const float* __restrict__ xv, const float* __restrict__ xc,
    const float* __restrict__ Wout, const float* __restrict__ bout,
    float* __restrict__ out)
{
    __shared__ float sW[64 * 65];
    __shared__ float sx[64 * 66];
    __shared__ float sb[64];
    __shared__ float sRc[64];
    const int tid = threadIdx.x;
    const int r0 = blockIdx.x * 64;

    for (int i = tid; i < 4096; i += 256) {
        int j = i >> 6, k = i & 63;
        sW[k * 65 + j] = Wout[i];
    }
    if (tid < 64) {
        sb[tid] = bout[tid];
        sRc[tid] = 1.0f / fmaxf(g_cnt[r0 + tid], 1.0f);
    }
    __syncthreads();
    for (int i = tid; i < 1024; i += 256) {
        int row = i >> 4, q4 = i & 15;
        float4 f = *(const float4*)&g_acc[(size_t)(r0 + row) * 64 + q4 * 4];
        float rc = sRc[row];
        int kb = q4 * 4;
        sx[(kb + 0) * 66 + row] = f.x * rc;
        sx[(kb + 1) * 66 + row] = f.y * rc;
        sx[(kb + 2) * 66 + row] = f.z * rc;
        sx[(kb + 3) * 66 + row] = f.w * rc;
    }
    __syncthreads();

    const int j = tid & 63;
    const int g = tid >> 6;

    ull a[8];
    #pragma unroll
    for (int p = 0; p < 8; ++p) a[p] = 0ull;

    #pragma unroll 4
    for (int k = 0; k < 64; ++k) {
        float w = sW[k * 65 + j];
        ull w2 = pk(w, w);
        #pragma unroll
        for (int p = 0; p < 8; ++p) {
            ull x2 = *(const ull*)&sx[k * 66 + g * 16 + 2 * p];
            a[p] = fma2(x2, w2, a[p]);
        }
    }

    float bj = sb[j];
    #pragma unroll
    for (int p = 0; p < 8; ++p) {
        int gr = r0 + g * 16 + 2 * p;
        float lo, hi;
        upk(a[p], lo, hi);
        float x0 = (gr < NV) ? xv[(size_t)gr * 64 + j]
                             : xc[(size_t)(gr - NV) * 64 + j];
        float x1 = (gr + 1 < NV) ? xv[(size_t)(gr + 1) * 64 + j]
                                 : xc[(size_t)(gr + 1 - NV) * 64 + j];
        out[(size_t)gr * 64 + j]       = x0 + bj + lo;
        out[(size_t)(gr + 1) * 64 + j] = x1 + bj + hi;
    }
}

// ---------------- launcher -------------------------------------------------
extern "C" void kernel_launch(void* const* d_in, const int* in_sizes, int n_in,
                              void* d_out, int out_size)
{
    const float* xv   = (const float*)d_in[0];
    const float* xc   = (const float*)d_in[1];
    // d_in[2] edge_index, d_in[3] edge_polarity: unused by reference
    const int*   cvi  = (const int*)d_in[4];
    const int*   cci  = (const int*)d_in[5];
    const float* sat  = (const float*)d_in[6];
    const int*   ah   = (const int*)d_in[7];
    const float* WQ   = (const float*)d_in[8];
    const float* WK   = (const float*)d_in[9];
    const float* WV   = (const float*)d_in[10];
    const float* hw   = (const float*)d_in[11];
    const float* Wout = (const float*)d_in[12];
    const float* bout = (const float*)d_in[13];
    float* out = (float*)d_out;

    const int qkv_smem = QKV_SMEM_FLOATS * 4;
    cudaFuncSetAttribute(qkv_kernel,  cudaFuncAttributeMaxDynamicSharedMemorySize, qkv_smem);
    cudaFuncSetAttribute(attn_kernel, cudaFuncAttributeMaxDynamicSharedMemorySize, ATTN_SMEM_BYTES);

    zero_kernel<<<(NTOT * D / 4 + 255) / 256, 256>>>();
    qkv_kernel<<<3125, 256, qkv_smem>>>(xv, xc, WQ, WK, WV);
    attn_kernel<<<CLUSTERS, 256, ATTN_SMEM_BYTES>>>(cvi, cci, sat, ah, hw);
    proj_kernel<<<3125, 256>>>(xv, xc, Wout, bout, out);
}

// round 5
// speedup vs baseline: 1.8426x; 1.5749x over previous
#include <cuda_runtime.h>
#include <cuda_bf16.h>
#include <cstdint>

#define NV 100000
#define NTOT 200000
#define CLUSTERS 2048
#define GAMMA 1.0f
#define NEG_SLOPE 0.2f

// ---------------- scratch (device globals; no allocation allowed) ----------
__device__ __align__(16) __nv_bfloat16 g_Qhi[NTOT * 64];
__device__ __align__(16) __nv_bfloat16 g_Qlo[NTOT * 64];
__device__ __align__(16) __nv_bfloat16 g_Khi[NTOT * 64];
__device__ __align__(16) __nv_bfloat16 g_Klo[NTOT * 64];
__device__ __align__(16) __nv_bfloat16 g_Vhi[NTOT * 64];
__device__ __align__(16) __nv_bfloat16 g_Vlo[NTOT * 64];
__device__ __align__(16) float g_acc[NTOT * 64];
__device__ __align__(16) float g_cnt[NTOT];

// split float pair into (hi, lo) bf16x2 words; lower half = first element
__device__ __forceinline__ void bf2split(float a, float b, uint32_t& hi, uint32_t& lo) {
    __nv_bfloat162 h = __floats2bfloat162_rn(a, b);
    float ha = __bfloat162float(__low2bfloat16(h));
    float hb = __bfloat162float(__high2bfloat16(h));
    __nv_bfloat162 l = __floats2bfloat162_rn(a - ha, b - hb);
    hi = *reinterpret_cast<uint32_t*>(&h);
    lo = *reinterpret_cast<uint32_t*>(&l);
}

// mma.sync m16n8k16 bf16 -> f32 accumulate
__device__ __forceinline__ void mma16816(float* c, uint32_t a0, uint32_t a1,
                                         uint32_t a2, uint32_t a3,
                                         uint32_t b0, uint32_t b1) {
    asm volatile(
        "mma.sync.aligned.m16n8k16.row.col.f32.bf16.bf16.f32 "
        "{%0,%1,%2,%3}, {%4,%5,%6,%7}, {%8,%9}, {%0,%1,%2,%3};"
        : "+f"(c[0]), "+f"(c[1]), "+f"(c[2]), "+f"(c[3])
        : "r"(a0), "r"(a1), "r"(a2), "r"(a3), "r"(b0), "r"(b1));
}

// ---------------- zero scratch --------------------------------------------
__global__ void zero_kernel() {
    int idx = blockIdx.x * blockDim.x + threadIdx.x;
    const int n4 = NTOT * 64 / 4;
    if (idx < n4) ((float4*)g_acc)[idx] = make_float4(0.f, 0.f, 0.f, 0.f);
    if (idx < NTOT) g_cnt[idx] = 0.f;
}

// ---------------- QKV via HMMA --------------------------------------------
// 256 threads, 128-row tile per CTA, warp = 16-row stripe.
// smem: xhi/xlo [128 rows][72 bf16] stride 144B; Whi/Wlo 3x[64][72].
#define QKV_XHI 0
#define QKV_XLO 18432
#define QKV_WHI 36864
#define QKV_WLO 64512
#define QKV_SMEM 92160

__global__ void __launch_bounds__(256, 2) qkv_kernel(
    const float* __restrict__ xv, const float* __restrict__ xc,
    const float* __restrict__ WQ, const float* __restrict__ WK,
    const float* __restrict__ WV)
{
    extern __shared__ char sm[];
    const int tid = threadIdx.x;
    const int wid = tid >> 5, lane = tid & 31;
    const int g = lane >> 2, t = lane & 3;
    const int m0 = wid * 16;
    const int r0 = blockIdx.x * 128;

    // ---- load + split weights ----
    {
        const float* Wsrc[3] = {WQ, WK, WV};
        for (int idx = tid; idx < 384; idx += 256) {
            int mat = idx >> 7;
            int rh  = idx & 127;
            int j = rh >> 1, h32 = (rh & 1) * 32;
            const float* w = Wsrc[mat] + j * 64 + h32;
            char* bhi = sm + QKV_WHI + mat * 9216 + j * 144 + h32 * 2;
            char* blo = sm + QKV_WLO + mat * 9216 + j * 144 + h32 * 2;
            #pragma unroll
            for (int i = 0; i < 8; ++i) {
                float4 f = *(const float4*)(w + i * 4);
                uint32_t hi, lo;
                bf2split(f.x, f.y, hi, lo);
                *(uint32_t*)(bhi + i * 8) = hi;
                *(uint32_t*)(blo + i * 8) = lo;
                bf2split(f.z, f.w, hi, lo);
                *(uint32_t*)(bhi + i * 8 + 4) = hi;
                *(uint32_t*)(blo + i * 8 + 4) = lo;
            }
        }
    }

    // ---- load + split x rows ----
    {
        int row = tid >> 1, h32 = (tid & 1) * 32;
        int gr = r0 + row;
        char* xhi = sm + QKV_XHI + row * 144 + h32 * 2;
        char* xlo = sm + QKV_XLO + row * 144 + h32 * 2;
        if (gr < NTOT) {
            const float* src = (gr < NV) ? xv + (size_t)gr * 64 + h32
                                         : xc + (size_t)(gr - NV) * 64 + h32;
            #pragma unroll
            for (int i = 0; i < 8; ++i) {
                float4 f = *(const float4*)(src + i * 4);
                uint32_t hi, lo;
                bf2split(f.x, f.y, hi, lo);
                *(uint32_t*)(xhi + i * 8) = hi;
                *(uint32_t*)(xlo + i * 8) = lo;
                bf2split(f.z, f.w, hi, lo);
                *(uint32_t*)(xhi + i * 8 + 4) = hi;
                *(uint32_t*)(xlo + i * 8 + 4) = lo;
            }
        } else {
            #pragma unroll
            for (int i = 0; i < 8; ++i) {
                *(uint64_t*)(xhi + i * 8) = 0ull;
                *(uint64_t*)(xlo + i * 8) = 0ull;
            }
        }
    }
    __syncthreads();

    const uint32_t rowA = (uint32_t)(m0 + g) * 144;
    const uint32_t rowB = rowA + 8 * 144;
    const int rA = r0 + m0 + g;
    const int rB = rA + 8;

    __nv_bfloat16* Ghi[3] = {g_Qhi, g_Khi, g_Vhi};
    __nv_bfloat16* Glo[3] = {g_Qlo, g_Klo, g_Vlo};

    #pragma unroll 1
    for (int mat = 0; mat < 3; ++mat) {
        float c[8][4];
        #pragma unroll
        for (int n = 0; n < 8; ++n)
            #pragma unroll
            for (int j = 0; j < 4; ++j) c[n][j] = 0.f;

        #pragma unroll 1
        for (int pass = 0; pass < 3; ++pass) {
            const char* xa = sm + ((pass == 2) ? QKV_XLO : QKV_XHI);
            const char* wb = sm + ((pass == 1) ? QKV_WLO : QKV_WHI) + mat * 9216;
            #pragma unroll
            for (int kc = 0; kc < 4; ++kc) {
                uint32_t ko = (uint32_t)kc * 32 + (uint32_t)t * 4;
                uint32_t a0 = *(const uint32_t*)(xa + rowA + ko);
                uint32_t a1 = *(const uint32_t*)(xa + rowB + ko);
                uint32_t a2 = *(const uint32_t*)(xa + rowA + ko + 16);
                uint32_t a3 = *(const uint32_t*)(xa + rowB + ko + 16);
                #pragma unroll
                for (int n = 0; n < 8; ++n) {
                    const char* wr = wb + (uint32_t)(8 * n + g) * 144 + ko;
                    mma16816(c[n], a0, a1, a2, a3,
                             *(const uint32_t*)wr, *(const uint32_t*)(wr + 16));
                }
            }
        }

        if (rA < NTOT) {
            #pragma unroll
            for (int n = 0; n < 8; ++n) {
                uint32_t hi, lo;
                bf2split(c[n][0], c[n][1], hi, lo);
                size_t off = (size_t)rA * 64 + 8 * n + 2 * t;
                *(uint32_t*)(Ghi[mat] + off) = hi;
                *(uint32_t*)(Glo[mat] + off) = lo;
            }
        }
        if (rB < NTOT) {
            #pragma unroll
            for (int n = 0; n < 8; ++n) {
                uint32_t hi, lo;
                bf2split(c[n][2], c[n][3], hi, lo);
                size_t off = (size_t)rB * 64 + 8 * n + 2 * t;
                *(uint32_t*)(Ghi[mat] + off) = hi;
                *(uint32_t*)(Glo[mat] + off) = lo;
            }
        }
    }
}

// ---------------- HMMA attention ------------------------------------------
#define A_QHI 0
#define A_QLO 18432
#define A_KHI 36864
#define A_KLO 55296
#define A_VHI 73728
#define A_VLO 91136
#define ATTN_SMEM_BYTES 108544

__global__ void __launch_bounds__(256) attn_kernel(
    const int* __restrict__ cvi, const int* __restrict__ cci,
    const float* __restrict__ sat, const int* __restrict__ active_heads,
    const float* __restrict__ head_weights)
{
    extern __shared__ char smc[];
    __shared__ int   sNode[128];
    __shared__ float sBias[128];
    __shared__ float sHw;

    const int tid  = threadIdx.x;
    const int wid  = tid >> 5;
    const int lane = tid & 31;
    const int c    = blockIdx.x;
    const int g    = lane >> 2;
    const int t    = lane & 3;
    const int m0   = wid * 16;

    if (tid < 64) {
        sNode[tid] = cvi[c * 64 + tid];
        sBias[tid] = 0.f;
    } else if (tid < 128) {
        int id = cci[c * 64 + tid - 64];
        sNode[tid] = NV + id;
        sBias[tid] = GAMMA * sat[id];
    }
    if (tid == 128) {
        int ah = active_heads[0];
        if (ah < 1) ah = 1;
        if (ah > 4) ah = 4;
        float s = 0.f;
        for (int h = 0; h < 4; ++h) if (h < ah) s += head_weights[h];
        sHw = s / (float)ah;
    }
    __syncthreads();

    // ---- gather (pure copy; data pre-split by qkv) ----
    {
        const int row = tid >> 1;
        const int h32 = (tid & 1) * 32;
        const int node = sNode[row];
        const size_t base = (size_t)node * 64 + h32;
        const uint32_t qoff = (uint32_t)row * 144 + (uint32_t)h32 * 2;

        const uint4* src;
        src = (const uint4*)(g_Qhi + base);
        #pragma unroll
        for (int i = 0; i < 4; ++i) *(uint4*)(smc + A_QHI + qoff + i * 16) = src[i];
        src = (const uint4*)(g_Qlo + base);
        #pragma unroll
        for (int i = 0; i < 4; ++i) *(uint4*)(smc + A_QLO + qoff + i * 16) = src[i];
        src = (const uint4*)(g_Khi + base);
        #pragma unroll
        for (int i = 0; i < 4; ++i) *(uint4*)(smc + A_KHI + qoff + i * 16) = src[i];
        src = (const uint4*)(g_Klo + base);
        #pragma unroll
        for (int i = 0; i < 4; ++i) *(uint4*)(smc + A_KLO + qoff + i * 16) = src[i];

        // V transposed into [d][row]
        src = (const uint4*)(g_Vhi + base);
        #pragma unroll
        for (int i = 0; i < 4; ++i) {
            uint4 v = src[i];
            uint32_t w[4] = {v.x, v.y, v.z, v.w};
            #pragma unroll
            for (int q = 0; q < 4; ++q) {
                int d = h32 + i * 8 + 2 * q;
                *(uint16_t*)(smc + A_VHI + (uint32_t)d * 272 + (uint32_t)row * 2) = (uint16_t)(w[q] & 0xffffu);
                *(uint16_t*)(smc + A_VHI + (uint32_t)(d + 1) * 272 + (uint32_t)row * 2) = (uint16_t)(w[q] >> 16);
            }
        }
        src = (const uint4*)(g_Vlo + base);
        #pragma unroll
        for (int i = 0; i < 4; ++i) {
            uint4 v = src[i];
            uint32_t w[4] = {v.x, v.y, v.z, v.w};
            #pragma unroll
            for (int q = 0; q < 4; ++q) {
                int d = h32 + i * 8 + 2 * q;
                *(uint16_t*)(smc + A_VLO + (uint32_t)d * 272 + (uint32_t)row * 2) = (uint16_t)(w[q] & 0xffffu);
                *(uint16_t*)(smc + A_VLO + (uint32_t)(d + 1) * 272 + (uint32_t)row * 2) = (uint16_t)(w[q] >> 16);
            }
        }
    }
    __syncthreads();

    // ---- S = Q K^T via 3-pass bf16-split HMMA ----
    float cS[16][4];
    #pragma unroll
    for (int n = 0; n < 16; ++n)
        #pragma unroll
        for (int j = 0; j < 4; ++j) cS[n][j] = 0.f;

    const uint32_t qrowA = (uint32_t)(m0 + g) * 144;
    const uint32_t qrowB = qrowA + 8 * 144;

    #pragma unroll 1
    for (int pass = 0; pass < 3; ++pass) {
        const char* qb = smc + ((pass == 2) ? A_QLO : A_QHI);
        const char* kb = smc + ((pass == 1) ? A_KLO : A_KHI);
        #pragma unroll
        for (int kc = 0; kc < 4; ++kc) {
            uint32_t ko = (uint32_t)kc * 32 + (uint32_t)t * 4;
            uint32_t a0 = *(const uint32_t*)(qb + qrowA + ko);
            uint32_t a1 = *(const uint32_t*)(qb + qrowB + ko);
            uint32_t a2 = *(const uint32_t*)(qb + qrowA + ko + 16);
            uint32_t a3 = *(const uint32_t*)(qb + qrowB + ko + 16);
            #pragma unroll
            for (int n = 0; n < 16; ++n) {
                const char* kr = kb + (uint32_t)(8 * n + g) * 144 + ko;
                uint32_t b0 = *(const uint32_t*)kr;
                uint32_t b1 = *(const uint32_t*)(kr + 16);
                mma16816(cS[n], a0, a1, a2, a3, b0, b1);
            }
        }
    }

    // ---- bias + leaky + softmax (register-resident) ----
    float mA = -1e30f, mB = -1e30f;
    #pragma unroll
    for (int n = 0; n < 16; ++n) {
        float b0v = sBias[8 * n + 2 * t];
        float b1v = sBias[8 * n + 2 * t + 1];
        float s;
        s = cS[n][0] * 0.125f + b0v; s = (s > 0.f) ? s : NEG_SLOPE * s; cS[n][0] = s; mA = fmaxf(mA, s);
        s = cS[n][1] * 0.125f + b1v; s = (s > 0.f) ? s : NEG_SLOPE * s; cS[n][1] = s; mA = fmaxf(mA, s);
        s = cS[n][2] * 0.125f + b0v; s = (s > 0.f) ? s : NEG_SLOPE * s; cS[n][2] = s; mB = fmaxf(mB, s);
        s = cS[n][3] * 0.125f + b1v; s = (s > 0.f) ? s : NEG_SLOPE * s; cS[n][3] = s; mB = fmaxf(mB, s);
    }
    mA = fmaxf(mA, __shfl_xor_sync(0xffffffffu, mA, 1));
    mA = fmaxf(mA, __shfl_xor_sync(0xffffffffu, mA, 2));
    mB = fmaxf(mB, __shfl_xor_sync(0xffffffffu, mB, 1));
    mB = fmaxf(mB, __shfl_xor_sync(0xffffffffu, mB, 2));

    float sA = 0.f, sB = 0.f;
    #pragma unroll
    for (int n = 0; n < 16; ++n) {
        cS[n][0] = __expf(cS[n][0] - mA); sA += cS[n][0];
        cS[n][1] = __expf(cS[n][1] - mA); sA += cS[n][1];
        cS[n][2] = __expf(cS[n][2] - mB); sB += cS[n][2];
        cS[n][3] = __expf(cS[n][3] - mB); sB += cS[n][3];
    }
    sA += __shfl_xor_sync(0xffffffffu, sA, 1);
    sA += __shfl_xor_sync(0xffffffffu, sA, 2);
    sB += __shfl_xor_sync(0xffffffffu, sB, 1);
    sB += __shfl_xor_sync(0xffffffffu, sB, 2);

    const float hw = sHw;
    const float scA = hw / sA;
    const float scB = hw / sB;

    uint32_t phi[16][2], plo[16][2];
    #pragma unroll
    for (int n = 0; n < 16; ++n) {
        bf2split(cS[n][0] * scA, cS[n][1] * scA, phi[n][0], plo[n][0]);
        bf2split(cS[n][2] * scB, cS[n][3] * scB, phi[n][1], plo[n][1]);
    }

    // ---- H = P V via 3-pass bf16-split HMMA ----
    float cH[8][4];
    #pragma unroll
    for (int n = 0; n < 8; ++n)
        #pragma unroll
        for (int j = 0; j < 4; ++j) cH[n][j] = 0.f;

    #pragma unroll 1
    for (int pass = 0; pass < 3; ++pass) {
        const uint32_t (*Pa)[2] = (pass == 2) ? plo : phi;
        const char* vb = smc + ((pass == 1) ? A_VLO : A_VHI);
        #pragma unroll
        for (int kc = 0; kc < 8; ++kc) {
            uint32_t a0 = Pa[2 * kc][0];
            uint32_t a1 = Pa[2 * kc][1];
            uint32_t a2 = Pa[2 * kc + 1][0];
            uint32_t a3 = Pa[2 * kc + 1][1];
            uint32_t ko = (uint32_t)kc * 32 + (uint32_t)t * 4;
            #pragma unroll
            for (int n = 0; n < 8; ++n) {
                const char* vr = vb + (uint32_t)(8 * n + g) * 272 + ko;
                uint32_t b0 = *(const uint32_t*)vr;
                uint32_t b1 = *(const uint32_t*)(vr + 16);
                mma16816(cH[n], a0, a1, a2, a3, b0, b1);
            }
        }
    }

    // ---- epilogue: scatter-add ----
    {
        int nodeA = sNode[m0 + g];
        int nodeB = sNode[m0 + g + 8];
        float* dA = g_acc + (size_t)nodeA * 64;
        float* dB = g_acc + (size_t)nodeB * 64;
        #pragma unroll
        for (int n = 0; n < 8; ++n) {
            int col = 8 * n + 2 * t;
            atomicAdd(dA + col,     cH[n][0]);
            atomicAdd(dA + col + 1, cH[n][1]);
            atomicAdd(dB + col,     cH[n][2]);
            atomicAdd(dB + col + 1, cH[n][3]);
        }
        if (t == 0) {
            atomicAdd(&g_cnt[nodeA], 1.0f);
            atomicAdd(&g_cnt[nodeB], 1.0f);
        }
    }
}

// ---------------- projection + residual via HMMA ---------------------------
#define PRJ_XHI 0
#define PRJ_XLO 18432
#define PRJ_WHI 36864
#define PRJ_WLO 46080
#define PRJ_SMEM 55296

__global__ void __launch_bounds__(256, 2) proj_kernel(
    const float* __restrict__ xv, const float* __restrict__ xc,
    const float* __restrict__ Wout, const float* __restrict__ bout,
    float* __restrict__ out)
{
    extern __shared__ char sm[];
    __shared__ float sb[64];
    const int tid = threadIdx.x;
    const int wid = tid >> 5, lane = tid & 31;
    const int g = lane >> 2, t = lane & 3;
    const int m0 = wid * 16;
    const int r0 = blockIdx.x * 128;

    if (tid < 64) sb[tid] = bout[tid];

    if (tid < 128) {
        int j = tid >> 1, h32 = (tid & 1) * 32;
        const float* w = Wout + j * 64 + h32;
        char* bhi = sm + PRJ_WHI + j * 144 + h32 * 2;
        char* blo = sm + PRJ_WLO + j * 144 + h32 * 2;
        #pragma unroll
        for (int i = 0; i < 8; ++i) {
            float4 f = *(const float4*)(w + i * 4);
            uint32_t hi, lo;
            bf2split(f.x, f.y, hi, lo);
            *(uint32_t*)(bhi + i * 8) = hi;
            *(uint32_t*)(blo + i * 8) = lo;
            bf2split(f.z, f.w, hi, lo);
            *(uint32_t*)(bhi + i * 8 + 4) = hi;
            *(uint32_t*)(blo + i * 8 + 4) = lo;
        }
    }

    {
        int row = tid >> 1, h32 = (tid & 1) * 32;
        int gr = r0 + row;
        char* xhi = sm + PRJ_XHI + row * 144 + h32 * 2;
        char* xlo = sm + PRJ_XLO + row * 144 + h32 * 2;
        if (gr < NTOT) {
            float rc = 1.0f / fmaxf(g_cnt[gr], 1.0f);
            const float* src = g_acc + (size_t)gr * 64 + h32;
            #pragma unroll
            for (int i = 0; i < 8; ++i) {
                float4 f = *(const float4*)(src + i * 4);
                uint32_t hi, lo;
                bf2split(f.x * rc, f.y * rc, hi, lo);
                *(uint32_t*)(xhi + i * 8) = hi;
                *(uint32_t*)(xlo + i * 8) = lo;
                bf2split(f.z * rc, f.w * rc, hi, lo);
                *(uint32_t*)(xhi + i * 8 + 4) = hi;
                *(uint32_t*)(xlo + i * 8 + 4) = lo;
            }
        } else {
            #pragma unroll
            for (int i = 0; i < 8; ++i) {
                *(uint64_t*)(xhi + i * 8) = 0ull;
                *(uint64_t*)(xlo + i * 8) = 0ull;
            }
        }
    }
    __syncthreads();

    const uint32_t rowA = (uint32_t)(m0 + g) * 144;
    const uint32_t rowB = rowA + 8 * 144;
    const int rA = r0 + m0 + g;
    const int rB = rA + 8;

    float c[8][4];
    #pragma unroll
    for (int n = 0; n < 8; ++n)
        #pragma unroll
        for (int j = 0; j < 4; ++j) c[n][j] = 0.f;

    #pragma unroll 1
    for (int pass = 0; pass < 3; ++pass) {
        const char* xa = sm + ((pass == 2) ? PRJ_XLO : PRJ_XHI);
        const char* wb = sm + ((pass == 1) ? PRJ_WLO : PRJ_WHI);
        #pragma unroll
        for (int kc = 0; kc < 4; ++kc) {
            uint32_t ko = (uint32_t)kc * 32 + (uint32_t)t * 4;
            uint32_t a0 = *(const uint32_t*)(xa + rowA + ko);
            uint32_t a1 = *(const uint32_t*)(xa + rowB + ko);
            uint32_t a2 = *(const uint32_t*)(xa + rowA + ko + 16);
            uint32_t a3 = *(const uint32_t*)(xa + rowB + ko + 16);
            #pragma unroll
            for (int n = 0; n < 8; ++n) {
                const char* wr = wb + (uint32_t)(8 * n + g) * 144 + ko;
                mma16816(c[n], a0, a1, a2, a3,
                         *(const uint32_t*)wr, *(const uint32_t*)(wr + 16));
            }
        }
    }

    if (rA < NTOT) {
        const float* xsrc = (rA < NV) ? xv + (size_t)rA * 64
                                      : xc + (size_t)(rA - NV) * 64;
        #pragma unroll
        for (int n = 0; n < 8; ++n) {
            int col = 8 * n + 2 * t;
            float2 xx = *(const float2*)(xsrc + col);
            float2 o;
            o.x = xx.x + sb[col] + c[n][0];
            o.y = xx.y + sb[col + 1] + c[n][1];
            *(float2*)(out + (size_t)rA * 64 + col) = o;
        }
    }
    if (rB < NTOT) {
        const float* xsrc = (rB < NV) ? xv + (size_t)rB * 64
                                      : xc + (size_t)(rB - NV) * 64;
        #pragma unroll
        for (int n = 0; n < 8; ++n) {
            int col = 8 * n + 2 * t;
            float2 xx = *(const float2*)(xsrc + col);
            float2 o;
            o.x = xx.x + sb[col] + c[n][2];
            o.y = xx.y + sb[col + 1] + c[n][3];
            *(float2*)(out + (size_t)rB * 64 + col) = o;
        }
    }
}

// ---------------- launcher -------------------------------------------------
extern "C" void kernel_launch(void* const* d_in, const int* in_sizes, int n_in,
                              void* d_out, int out_size)
{
    const float* xv   = (const float*)d_in[0];
    const float* xc   = (const float*)d_in[1];
    // d_in[2] edge_index, d_in[3] edge_polarity: unused by reference
    const int*   cvi  = (const int*)d_in[4];
    const int*   cci  = (const int*)d_in[5];
    const float* sat  = (const float*)d_in[6];
    const int*   ah   = (const int*)d_in[7];
    const float* WQ   = (const float*)d_in[8];
    const float* WK   = (const float*)d_in[9];
    const float* WV   = (const float*)d_in[10];
    const float* hw   = (const float*)d_in[11];
    const float* Wout = (const float*)d_in[12];
    const float* bout = (const float*)d_in[13];
    float* out = (float*)d_out;

    cudaFuncSetAttribute(qkv_kernel,  cudaFuncAttributeMaxDynamicSharedMemorySize, QKV_SMEM);
    cudaFuncSetAttribute(attn_kernel, cudaFuncAttributeMaxDynamicSharedMemorySize, ATTN_SMEM_BYTES);
    cudaFuncSetAttribute(proj_kernel, cudaFuncAttributeMaxDynamicSharedMemorySize, PRJ_SMEM);

    const int tiles = (NTOT + 127) / 128;   // 1563
    zero_kernel<<<(NTOT * 64 / 4 + 255) / 256, 256>>>();
    qkv_kernel<<<tiles, 256, QKV_SMEM>>>(xv, xc, WQ, WK, WV);
    attn_kernel<<<CLUSTERS, 256, ATTN_SMEM_BYTES>>>(cvi, cci, sat, ah, hw);
    proj_kernel<<<tiles, 256, PRJ_SMEM>>>(xv, xc, Wout, bout, out);
}

// round 7
// speedup vs baseline: 1.8896x; 1.0255x over previous
#include <cuda_runtime.h>
#include <cuda_bf16.h>
#include <cstdint>

#define NV 100000
#define NTOT 200000
#define CLUSTERS 2048
#define GAMMA 1.0f
#define NEG_SLOPE 0.2f

// ---------------- scratch (device globals; no allocation allowed) ----------
// per node: Qhi(64) Qlo(64) Khi(64) Klo(64) Vhi(64) Vlo(64) bf16 = 768 B
__device__ __align__(16) __nv_bfloat16 g_QKV[(size_t)NTOT * 384];
__device__ __align__(16) float g_acc[(size_t)NTOT * 64];
__device__ __align__(16) float g_cnt[NTOT];

// split float pair into (hi, lo) bf16x2 words; lower half = first element
__device__ __forceinline__ void bf2split(float a, float b, uint32_t& hi, uint32_t& lo) {
    __nv_bfloat162 h = __floats2bfloat162_rn(a, b);
    float ha = __bfloat162float(__low2bfloat16(h));
    float hb = __bfloat162float(__high2bfloat16(h));
    __nv_bfloat162 l = __floats2bfloat162_rn(a - ha, b - hb);
    hi = *reinterpret_cast<uint32_t*>(&h);
    lo = *reinterpret_cast<uint32_t*>(&l);
}

__device__ __forceinline__ void mma16816(float* c, uint32_t a0, uint32_t a1,
                                         uint32_t a2, uint32_t a3,
                                         uint32_t b0, uint32_t b1) {
    asm volatile(
        "mma.sync.aligned.m16n8k16.row.col.f32.bf16.bf16.f32 "
        "{%0,%1,%2,%3}, {%4,%5,%6,%7}, {%8,%9}, {%0,%1,%2,%3};"
        : "+f"(c[0]), "+f"(c[1]), "+f"(c[2]), "+f"(c[3])
        : "r"(a0), "r"(a1), "r"(a2), "r"(a3), "r"(b0), "r"(b1));
}

__device__ __forceinline__ uint32_t smem_u32(const void* p) {
    uint32_t a;
    asm("{ .reg .u64 t; cvta.to.shared.u64 t, %1; cvt.u32.u64 %0, t; }"
        : "=r"(a) : "l"(p));
    return a;
}

// ---------------- QKV via HMMA + fused zeroing -----------------------------
// 256 threads, 128-row tile per CTA.
#define QKV_XHI 0
#define QKV_XLO 18432
#define QKV_WHI 36864
#define QKV_WLO 64512
#define QKV_SMEM 92160

__global__ void __launch_bounds__(256, 2) qkv_kernel(
    const float* __restrict__ xv, const float* __restrict__ xc,
    const float* __restrict__ WQ, const float* __restrict__ WK,
    const float* __restrict__ WV)
{
    extern __shared__ char sm[];
    const int tid = threadIdx.x;
    const int wid = tid >> 5, lane = tid & 31;
    const int g = lane >> 2, t = lane & 3;
    const int m0 = wid * 16;
    const int r0 = blockIdx.x * 128;

    // ---- fused zero of g_acc / g_cnt for this row slice ----
    {
        const size_t f4base = (size_t)r0 * 16;
        #pragma unroll
        for (int i = 0; i < 8; ++i) {
            size_t idx = f4base + tid + i * 256;
            if (idx < (size_t)NTOT * 16)
                ((float4*)g_acc)[idx] = make_float4(0.f, 0.f, 0.f, 0.f);
        }
        if (tid < 128 && r0 + tid < NTOT) g_cnt[r0 + tid] = 0.f;
    }

    // ---- load + split weights ----
    {
        const float* Wsrc[3] = {WQ, WK, WV};
        for (int idx = tid; idx < 384; idx += 256) {
            int mat = idx >> 7;
            int rh  = idx & 127;
            int j = rh >> 1, h32 = (rh & 1) * 32;
            const float* w = Wsrc[mat] + j * 64 + h32;
            char* bhi = sm + QKV_WHI + mat * 9216 + j * 144 + h32 * 2;
            char* blo = sm + QKV_WLO + mat * 9216 + j * 144 + h32 * 2;
            #pragma unroll
            for (int i = 0; i < 8; ++i) {
                float4 f = *(const float4*)(w + i * 4);
                uint32_t h0, l0, h1, l1;
                bf2split(f.x, f.y, h0, l0);
                bf2split(f.z, f.w, h1, l1);
                *(uint2*)(bhi + i * 8) = make_uint2(h0, h1);
                *(uint2*)(blo + i * 8) = make_uint2(l0, l1);
            }
        }
    }

    // ---- load + split x rows ----
    {
        int row = tid >> 1, h32 = (tid & 1) * 32;
        int gr = r0 + row;
        char* xhi = sm + QKV_XHI + row * 144 + h32 * 2;
        char* xlo = sm + QKV_XLO + row * 144 + h32 * 2;
        if (gr < NTOT) {
            const float* src = (gr < NV) ? xv + (size_t)gr * 64 + h32
                                         : xc + (size_t)(gr - NV) * 64 + h32;
            #pragma unroll
            for (int i = 0; i < 8; ++i) {
                float4 f = *(const float4*)(src + i * 4);
                uint32_t h0, l0, h1, l1;
                bf2split(f.x, f.y, h0, l0);
                bf2split(f.z, f.w, h1, l1);
                *(uint2*)(xhi + i * 8) = make_uint2(h0, h1);
                *(uint2*)(xlo + i * 8) = make_uint2(l0, l1);
            }
        } else {
            #pragma unroll
            for (int i = 0; i < 8; ++i) {
                *(uint64_t*)(xhi + i * 8) = 0ull;
                *(uint64_t*)(xlo + i * 8) = 0ull;
            }
        }
    }
    __syncthreads();

    const uint32_t rowA = (uint32_t)(m0 + g) * 144;
    const uint32_t rowB = rowA + 8 * 144;
    const int rA = r0 + m0 + g;
    const int rB = rA + 8;

    #pragma unroll 1
    for (int mat = 0; mat < 3; ++mat) {
        float c[8][4];
        #pragma unroll
        for (int n = 0; n < 8; ++n)
            #pragma unroll
            for (int j = 0; j < 4; ++j) c[n][j] = 0.f;

        #pragma unroll 1
        for (int pass = 0; pass < 3; ++pass) {
            const char* xa = sm + ((pass == 2) ? QKV_XLO : QKV_XHI);
            const char* wb = sm + ((pass == 1) ? QKV_WLO : QKV_WHI) + mat * 9216;
            #pragma unroll
            for (int kc = 0; kc < 4; ++kc) {
                uint32_t ko = (uint32_t)kc * 32 + (uint32_t)t * 4;
                uint32_t a0 = *(const uint32_t*)(xa + rowA + ko);
                uint32_t a1 = *(const uint32_t*)(xa + rowB + ko);
                uint32_t a2 = *(const uint32_t*)(xa + rowA + ko + 16);
                uint32_t a3 = *(const uint32_t*)(xa + rowB + ko + 16);
                #pragma unroll
                for (int n = 0; n < 8; ++n) {
                    const char* wr = wb + (uint32_t)(8 * n + g) * 144 + ko;
                    mma16816(c[n], a0, a1, a2, a3,
                             *(const uint32_t*)wr, *(const uint32_t*)(wr + 16));
                }
            }
        }

        if (rA < NTOT) {
            #pragma unroll
            for (int n = 0; n < 8; ++n) {
                uint32_t hi, lo;
                bf2split(c[n][0], c[n][1], hi, lo);
                size_t off = (size_t)rA * 384 + mat * 128 + 8 * n + 2 * t;
                *(uint32_t*)(g_QKV + off)      = hi;
                *(uint32_t*)(g_QKV + off + 64) = lo;
            }
        }
        if (rB < NTOT) {
            #pragma unroll
            for (int n = 0; n < 8; ++n) {
                uint32_t hi, lo;
                bf2split(c[n][2], c[n][3], hi, lo);
                size_t off = (size_t)rB * 384 + mat * 128 + 8 * n + 2 * t;
                *(uint32_t*)(g_QKV + off)      = hi;
                *(uint32_t*)(g_QKV + off + 64) = lo;
            }
        }
    }
}

// ---------------- HMMA attention ------------------------------------------
// smem: 3 tensors (Q, K, V), each [128 rows][272 B]: hi 128B | lo 128B | 16B pad
#define SQ 0
#define SK 34816
#define SV 69632
#define ATTN_SMEM_BYTES 104448

__global__ void __launch_bounds__(256) attn_kernel(
    const int* __restrict__ cvi, const int* __restrict__ cci,
    const float* __restrict__ sat, const int* __restrict__ active_heads,
    const float* __restrict__ head_weights)
{
    extern __shared__ char smc[];
    __shared__ int   sNode[128];
    __shared__ float sBias[128];
    __shared__ float sHw;

    const int tid  = threadIdx.x;
    const int wid  = tid >> 5;
    const int lane = tid & 31;
    const int c    = blockIdx.x;
    const int g    = lane >> 2;
    const int t    = lane & 3;
    const int m0   = wid * 16;

    if (tid < 64) {
        sNode[tid] = cvi[c * 64 + tid];
        sBias[tid] = 0.f;
    } else if (tid < 128) {
        int id = cci[c * 64 + tid - 64];
        sNode[tid] = NV + id;
        sBias[tid] = GAMMA * sat[id];
    }
    if (tid == 128) {
        int ah = active_heads[0];
        if (ah < 1) ah = 1;
        if (ah > 4) ah = 4;
        float s = 0.f;
        for (int h = 0; h < 4; ++h) if (h < ah) s += head_weights[h];
        sHw = s / (float)ah;
    }
    __syncthreads();

    // ---- gather: one contiguous 768B block per node, pure uint4 copies ----
    // Two threads per row; each copies 24 uint4 -> full 768 bytes covered.
    {
        const int row = tid >> 1;
        const int h   = tid & 1;
        const int node = sNode[row];
        const char* src = (const char*)g_QKV + (size_t)node * 768;
        #pragma unroll
        for (int i = 0; i < 24; ++i) {
            int gb = (i * 2 + h) * 16;        // 0..752
            int part = gb >> 7;               // 0..5
            int tau = part >> 1;              // 0=Q,1=K,2=V
            int which = part & 1;             // 0=hi,1=lo
            int within = gb & 127;
            uint4 v = *(const uint4*)(src + gb);
            *(uint4*)(smc + tau * 34816 + row * 272 + which * 128 + within) = v;
        }
    }
    __syncthreads();

    // ---- S = Q K^T via 3-pass bf16-split HMMA ----
    float cS[16][4];
    #pragma unroll
    for (int n = 0; n < 16; ++n)
        #pragma unroll
        for (int j = 0; j < 4; ++j) cS[n][j] = 0.f;

    const uint32_t qrowA = (uint32_t)(m0 + g) * 272;
    const uint32_t qrowB = qrowA + 8 * 272;

    #pragma unroll 1
    for (int pass = 0; pass < 3; ++pass) {
        const char* qb = smc + SQ + ((pass == 2) ? 128 : 0);
        const char* kb = smc + SK + ((pass == 1) ? 128 : 0);
        #pragma unroll
        for (int kc = 0; kc < 4; ++kc) {
            uint32_t ko = (uint32_t)kc * 32 + (uint32_t)t * 4;
            uint32_t a0 = *(const uint32_t*)(qb + qrowA + ko);
            uint32_t a1 = *(const uint32_t*)(qb + qrowB + ko);
            uint32_t a2 = *(const uint32_t*)(qb + qrowA + ko + 16);
            uint32_t a3 = *(const uint32_t*)(qb + qrowB + ko + 16);
            #pragma unroll
            for (int n = 0; n < 16; ++n) {
                const char* kr = kb + (uint32_t)(8 * n + g) * 272 + ko;
                uint32_t b0 = *(const uint32_t*)kr;
                uint32_t b1 = *(const uint32_t*)(kr + 16);
                mma16816(cS[n], a0, a1, a2, a3, b0, b1);
            }
        }
    }

    // ---- bias + leaky + softmax (register-resident) ----
    float mA = -1e30f, mB = -1e30f;
    #pragma unroll
    for (int n = 0; n < 16; ++n) {
        float b0v = sBias[8 * n + 2 * t];
        float b1v = sBias[8 * n + 2 * t + 1];
        float s;
        s = cS[n][0] * 0.125f + b0v; s = (s > 0.f) ? s : NEG_SLOPE * s; cS[n][0] = s; mA = fmaxf(mA, s);
        s = cS[n][1] * 0.125f + b1v; s = (s > 0.f) ? s : NEG_SLOPE * s; cS[n][1] = s; mA = fmaxf(mA, s);
        s = cS[n][2] * 0.125f + b0v; s = (s > 0.f) ? s : NEG_SLOPE * s; cS[n][2] = s; mB = fmaxf(mB, s);
        s = cS[n][3] * 0.125f + b1v; s = (s > 0.f) ? s : NEG_SLOPE * s; cS[n][3] = s; mB = fmaxf(mB, s);
    }
    mA = fmaxf(mA, __shfl_xor_sync(0xffffffffu, mA, 1));
    mA = fmaxf(mA, __shfl_xor_sync(0xffffffffu, mA, 2));
    mB = fmaxf(mB, __shfl_xor_sync(0xffffffffu, mB, 1));
    mB = fmaxf(mB, __shfl_xor_sync(0xffffffffu, mB, 2));

    float sA = 0.f, sB = 0.f;
    #pragma unroll
    for (int n = 0; n < 16; ++n) {
        cS[n][0] = __expf(cS[n][0] - mA); sA += cS[n][0];
        cS[n][1] = __expf(cS[n][1] - mA); sA += cS[n][1];
        cS[n][2] = __expf(cS[n][2] - mB); sB += cS[n][2];
        cS[n][3] = __expf(cS[n][3] - mB); sB += cS[n][3];
    }
    sA += __shfl_xor_sync(0xffffffffu, sA, 1);
    sA += __shfl_xor_sync(0xffffffffu, sA, 2);
    sB += __shfl_xor_sync(0xffffffffu, sB, 1);
    sB += __shfl_xor_sync(0xffffffffu, sB, 2);

    const float hw = sHw;
    const float scA = hw / sA;
    const float scB = hw / sB;

    uint32_t phi[16][2], plo[16][2];
    #pragma unroll
    for (int n = 0; n < 16; ++n) {
        bf2split(cS[n][0] * scA, cS[n][1] * scA, phi[n][0], plo[n][0]);
        bf2split(cS[n][2] * scB, cS[n][3] * scB, phi[n][1], plo[n][1]);
    }

    // ---- H = P V via 3-pass HMMA; V B-fragments via ldmatrix.x2.trans ----
    float cH[8][4];
    #pragma unroll
    for (int n = 0; n < 8; ++n)
        #pragma unroll
        for (int j = 0; j < 4; ++j) cH[n][j] = 0.f;

    const uint32_t vbase = smem_u32(smc + SV);
    const uint32_t vlane = (uint32_t)(lane & 15);

    #pragma unroll 1
    for (int pass = 0; pass < 3; ++pass) {
        const uint32_t (*Pa)[2] = (pass == 2) ? plo : phi;
        const uint32_t voff = (pass == 1) ? 128u : 0u;
        #pragma unroll
        for (int kc = 0; kc < 8; ++kc) {
            uint32_t a0 = Pa[2 * kc][0];
            uint32_t a1 = Pa[2 * kc][1];
            uint32_t a2 = Pa[2 * kc + 1][0];
            uint32_t a3 = Pa[2 * kc + 1][1];
            uint32_t rowadr = vbase + ((uint32_t)kc * 16 + vlane) * 272 + voff;
            #pragma unroll
            for (int n = 0; n < 8; ++n) {
                uint32_t b0, b1;
                asm volatile(
                    "ldmatrix.sync.aligned.m8n8.x2.trans.shared.b16 {%0,%1}, [%2];"
                    : "=r"(b0), "=r"(b1) : "r"(rowadr + (uint32_t)n * 16));
                mma16816(cH[n], a0, a1, a2, a3, b0, b1);
            }
        }
    }

    // ---- epilogue: scatter-add ----
    {
        int nodeA = sNode[m0 + g];
        int nodeB = sNode[m0 + g + 8];
        float* dA = g_acc + (size_t)nodeA * 64;
        float* dB = g_acc + (size_t)nodeB * 64;
        #pragma unroll
        for (int n = 0; n < 8; ++n) {
            int col = 8 * n + 2 * t;
            atomicAdd(dA + col,     cH[n][0]);
            atomicAdd(dA + col + 1, cH[n][1]);
            atomicAdd(dB + col,     cH[n][2]);
            atomicAdd(dB + col + 1, cH[n][3]);
        }
        if (t == 0) {
            atomicAdd(&g_cnt[nodeA], 1.0f);
            atomicAdd(&g_cnt[nodeB], 1.0f);
        }
    }
}

// ---------------- projection + residual via HMMA ---------------------------
#define PRJ_XHI 0
#define PRJ_XLO 18432
#define PRJ_WHI 36864
#define PRJ_WLO 46080
#define PRJ_SMEM 55296

__global__ void __launch_bounds__(256, 3) proj_kernel(
    const float* __restrict__ xv, const float* __restrict__ xc,
    const float* __restrict__ Wout, const float* __restrict__ bout,
    float* __restrict__ out)
{
    extern __shared__ char sm[];
    __shared__ float sb[64];
    const int tid = threadIdx.x;
    const int wid = tid >> 5, lane = tid & 31;
    const int g = lane >> 2, t = lane & 3;
    const int m0 = wid * 16;
    const int r0 = blockIdx.x * 128;

    if (tid < 64) sb[tid] = bout[tid];

    if (tid < 128) {
        int j = tid >> 1, h32 = (tid & 1) * 32;
        const float* w = Wout + j * 64 + h32;
        char* bhi = sm + PRJ_WHI + j * 144 + h32 * 2;
        char* blo = sm + PRJ_WLO + j * 144 + h32 * 2;
        #pragma unroll
        for (int i = 0; i < 8; ++i) {
            float4 f = *(const float4*)(w + i * 4);
            uint32_t h0, l0, h1, l1;
            bf2split(f.x, f.y, h0, l0);
            bf2split(f.z, f.w, h1, l1);
            *(uint2*)(bhi + i * 8) = make_uint2(h0, h1);
            *(uint2*)(blo + i * 8) = make_uint2(l0, l1);
        }
    }

    {
        int row = tid >> 1, h32 = (tid & 1) * 32;
        int gr = r0 + row;
        char* xhi = sm + PRJ_XHI + row * 144 + h32 * 2;
        char* xlo = sm + PRJ_XLO + row * 144 + h32 * 2;
        if (gr < NTOT) {
            float rc = 1.0f / fmaxf(g_cnt[gr], 1.0f);
            const float* src = g_acc + (size_t)gr * 64 + h32;
            #pragma unroll
            for (int i = 0; i < 8; ++i) {
                float4 f = *(const float4*)(src + i * 4);
                uint32_t h0, l0, h1, l1;
                bf2split(f.x * rc, f.y * rc, h0, l0);
                bf2split(f.z * rc, f.w * rc, h1, l1);
                *(uint2*)(xhi + i * 8) = make_uint2(h0, h1);
                *(uint2*)(xlo + i * 8) = make_uint2(l0, l1);
            }
        } else {
            #pragma unroll
            for (int i = 0; i < 8; ++i) {
                *(uint64_t*)(xhi + i * 8) = 0ull;
                *(uint64_t*)(xlo + i * 8) = 0ull;
            }
        }
    }
    __syncthreads();

    const uint32_t rowA = (uint32_t)(m0 + g) * 144;
    const uint32_t rowB = rowA + 8 * 144;
    const int rA = r0 + m0 + g;
    const int rB = rA + 8;

    float c[8][4];
    #pragma unroll
    for (int n = 0; n < 8; ++n)
        #pragma unroll
        for (int j = 0; j < 4; ++j) c[n][j] = 0.f;

    #pragma unroll 1
    for (int pass = 0; pass < 3; ++pass) {
        const char* xa = sm + ((pass == 2) ? PRJ_XLO : PRJ_XHI);
        const char* wb = sm + ((pass == 1) ? PRJ_WLO : PRJ_WHI);
        #pragma unroll
        for (int kc = 0; kc < 4; ++kc) {
            uint32_t ko = (uint32_t)kc * 32 + (uint32_t)t * 4;
            uint32_t a0 = *(const uint32_t*)(xa + rowA + ko);
            uint32_t a1 = *(const uint32_t*)(xa + rowB + ko);
            uint32_t a2 = *(const uint32_t*)(xa + rowA + ko + 16);
            uint32_t a3 = *(const uint32_t*)(xa + rowB + ko + 16);
            #pragma unroll
            for (int n = 0; n < 8; ++n) {
                const char* wr = wb + (uint32_t)(8 * n + g) * 144 + ko;
                mma16816(c[n], a0, a1, a2, a3,
                         *(const uint32_t*)wr, *(const uint32_t*)(wr + 16));
            }
        }
    }

    if (rA < NTOT) {
        const float* xsrc = (rA < NV) ? xv + (size_t)rA * 64
                                      : xc + (size_t)(rA - NV) * 64;
        #pragma unroll
        for (int n = 0; n < 8; ++n) {
            int col = 8 * n + 2 * t;
            float2 xx = *(const float2*)(xsrc + col);
            float2 o;
            o.x = xx.x + sb[col] + c[n][0];
            o.y = xx.y + sb[col + 1] + c[n][1];
            *(float2*)(out + (size_t)rA * 64 + col) = o;
        }
    }
    if (rB < NTOT) {
        const float* xsrc = (rB < NV) ? xv + (size_t)rB * 64
                                      : xc + (size_t)(rB - NV) * 64;
        #pragma unroll
        for (int n = 0; n < 8; ++n) {
            int col = 8 * n + 2 * t;
            float2 xx = *(const float2*)(xsrc + col);
            float2 o;
            o.x = xx.x + sb[col] + c[n][2];
            o.y = xx.y + sb[col + 1] + c[n][3];
            *(float2*)(out + (size_t)rB * 64 + col) = o;
        }
    }
}

// ---------------- launcher -------------------------------------------------
extern "C" void kernel_launch(void* const* d_in, const int* in_sizes, int n_in,
                              void* d_out, int out_size)
{
    const float* xv   = (const float*)d_in[0];
    const float* xc   = (const float*)d_in[1];
    // d_in[2] edge_index, d_in[3] edge_polarity: unused by reference
    const int*   cvi  = (const int*)d_in[4];
    const int*   cci  = (const int*)d_in[5];
    const float* sat  = (const float*)d_in[6];
    const int*   ah   = (const int*)d_in[7];
    const float* WQ   = (const float*)d_in[8];
    const float* WK   = (const float*)d_in[9];
    const float* WV   = (const float*)d_in[10];
    const float* hw   = (const float*)d_in[11];
    const float* Wout = (const float*)d_in[12];
    const float* bout = (const float*)d_in[13];
    float* out = (float*)d_out;

    cudaFuncSetAttribute(qkv_kernel,  cudaFuncAttributeMaxDynamicSharedMemorySize, QKV_SMEM);
    cudaFuncSetAttribute(attn_kernel, cudaFuncAttributeMaxDynamicSharedMemorySize, ATTN_SMEM_BYTES);
    cudaFuncSetAttribute(proj_kernel, cudaFuncAttributeMaxDynamicSharedMemorySize, PRJ_SMEM);

    const int tiles = (NTOT + 127) / 128;   // 1563
    qkv_kernel<<<tiles, 256, QKV_SMEM>>>(xv, xc, WQ, WK, WV);
    attn_kernel<<<CLUSTERS, 256, ATTN_SMEM_BYTES>>>(cvi, cci, sat, ah, hw);
    proj_kernel<<<tiles, 256, PRJ_SMEM>>>(xv, xc, Wout, bout, out);
}